// round 1
// baseline (speedup 1.0000x reference)
#include <cuda_runtime.h>
#include <math.h>

#define F8c   16
#define F2c   64
#define DIM6c 455
#define Gc    4096
#define MROWS 8192     // B*T*F8
#define BTc   512      // B*T
#define XROWS 16384    // B*H*C
#define TROWS 32768    // B*T*F2

// -------- scratch (static device allocations are allowed) --------
__device__ float g_H [MROWS * 10];
__device__ float g_HH[MROWS * DIM6c];
__device__ float g_TJ[BTc * F2c * DIM6c];

// ================= kernel H: build per-row 10-vectors =================
// row = (b*T + t)*16 + c
// H[row][0]        = s * w1s[c]                       (fan_in 1)
// H[row][1+v*3+m]  = (1/sqrt(3)) * sum_u traj[u*3+m] * w1v[c,u,v]
__global__ void kH(const float* __restrict__ traj,
                   const float* __restrict__ w1s,
                   const float* __restrict__ w1v) {
    int row = blockIdx.x * blockDim.x + threadIdx.x;
    if (row >= MROWS) return;
    int bt = row >> 4, c = row & 15;
    const float* tr = traj + bt * 10;
    float t0 = tr[0], t1 = tr[1], t2 = tr[2], t3 = tr[3], t4 = tr[4],
          t5 = tr[5], t6 = tr[6], t7 = tr[7], t8 = tr[8], s = tr[9];
    float tv[9] = {t0,t1,t2,t3,t4,t5,t6,t7,t8};
    float* out = g_H + row * 10;
    out[0] = s * w1s[c];
    const float inv3 = 0.57735026918962576f;
    #pragma unroll
    for (int v = 0; v < 3; v++) {
        #pragma unroll
        for (int m = 0; m < 3; m++) {
            float a = 0.f;
            #pragma unroll
            for (int u = 0; u < 3; u++)
                a += tv[u*3 + m] * w1v[c*9 + u*3 + v];
            out[1 + v*3 + m] = a * inv3;
        }
    }
}

// ============ kernel B: HH = relu(H @ Din^T) @ Dout  (8192x4096x455) ============
// BLK_M=64, BLK_N=128, BLK_K=32; 256 threads; thread tile 4x8
__global__ __launch_bounds__(256) void kB(const float* __restrict__ Din,
                                          const float* __restrict__ Dout) {
    __shared__ float Hs[64][10];
    __shared__ float sig_s[32][68];    // [kk][m], 68 pad -> 16B aligned rows
    __shared__ float dout_s[32][128];

    const int m0 = blockIdx.x * 64;
    const int n0 = blockIdx.y * 128;
    const int tid = threadIdx.x;

    for (int i = tid; i < 64*10; i += 256)
        Hs[i/10][i%10] = g_H[m0*10 + i];
    __syncthreads();

    float acc[4][8];
    #pragma unroll
    for (int i = 0; i < 4; i++)
        #pragma unroll
        for (int j = 0; j < 8; j++) acc[i][j] = 0.f;

    const int tm = (tid & 15) * 4;
    const int tn = (tid >> 4) * 8;

    for (int k0 = 0; k0 < Gc; k0 += 32) {
        // stage Dout chunk [32 x 128]
        #pragma unroll
        for (int i = 0; i < 16; i++) {
            int idx = tid + i*256;
            int kk = idx >> 7, n = idx & 127;
            int gn = n0 + n;
            dout_s[kk][n] = (gn < DIM6c) ? Dout[(size_t)(k0+kk)*DIM6c + gn] : 0.f;
        }
        // compute sig chunk [32 x 64]: each thread does one kk, 8 m's
        {
            int kk = tid >> 3;
            int mb = (tid & 7) * 8;
            float dr[10];
            #pragma unroll
            for (int q = 0; q < 10; q++) dr[q] = Din[(k0+kk)*10 + q];
            #pragma unroll
            for (int j = 0; j < 8; j++) {
                int m = mb + j;
                float a = 0.f;
                #pragma unroll
                for (int q = 0; q < 10; q++) a += Hs[m][q] * dr[q];
                sig_s[kk][m] = fmaxf(a, 0.f);
            }
        }
        __syncthreads();
        #pragma unroll
        for (int kk = 0; kk < 32; kk++) {
            float4 a4 = *(const float4*)&sig_s[kk][tm];
            float av[4] = {a4.x, a4.y, a4.z, a4.w};
            float4 b0 = *(const float4*)&dout_s[kk][tn];
            float4 b1 = *(const float4*)&dout_s[kk][tn+4];
            float bv[8] = {b0.x,b0.y,b0.z,b0.w, b1.x,b1.y,b1.z,b1.w};
            #pragma unroll
            for (int i = 0; i < 4; i++)
                #pragma unroll
                for (int j = 0; j < 8; j++)
                    acc[i][j] += av[i] * bv[j];
        }
        __syncthreads();
    }
    #pragma unroll
    for (int i = 0; i < 4; i++) {
        #pragma unroll
        for (int j = 0; j < 8; j++) {
            int gn = n0 + tn + j;
            if (gn < DIM6c)
                g_HH[(size_t)(m0 + tm + i)*DIM6c + gn] = acc[i][j];
        }
    }
}

// ============ kernel C: per-l equi_linear with w2 ============
// out[bt,g2, o+v*d+m] = (1/sqrt(16d)) * sum_{f,u} HH[bt,f,o+u*d+m] * w2[f,g2,u,v]
// One CTA per bt; HH slice in smem; threads own (g2, v-pair), reuse w2 over m.
template<int L, int OFF>
__global__ __launch_bounds__(256) void kC(const float* __restrict__ w2) {
    constexpr int d = 2*L + 1;
    constexpr int PAIRS = (d + 1) / 2;
    __shared__ float HHs[F8c * DIM6c];     // 7280 floats
    const int bt = blockIdx.x;
    for (int i = threadIdx.x; i < F8c*DIM6c; i += 256)
        HHs[i] = g_HH[(size_t)bt * F8c * DIM6c + i];
    __syncthreads();

    const float scale = 0.25f * rsqrtf((float)d);

    for (int idx = threadIdx.x; idx < 64 * PAIRS; idx += 256) {
        int g2 = idx / PAIRS;
        int vp = idx - g2 * PAIRS;
        int v0 = vp * 2;
        const bool hasv1 = (v0 + 1 < d);
        float acc0[d], acc1[d];
        #pragma unroll
        for (int m = 0; m < d; m++) { acc0[m] = 0.f; acc1[m] = 0.f; }

        for (int f = 0; f < F8c; f++) {
            const float* wb = w2 + ((size_t)(f*64 + g2) * d) * d;
            const float* hb = HHs + f*DIM6c + OFF;
            #pragma unroll
            for (int u = 0; u < d; u++) {
                float w0 = wb[u*d + v0];
                float w1 = hasv1 ? wb[u*d + v0 + 1] : 0.f;
                #pragma unroll
                for (int m = 0; m < d; m++) {
                    float h = hb[u*d + m];
                    acc0[m] += h * w0;
                    acc1[m] += h * w1;
                }
            }
        }
        float* out = g_TJ + ((size_t)(bt*64 + g2)) * DIM6c + OFF;
        #pragma unroll
        for (int m = 0; m < d; m++) {
            out[v0*d + m] = acc0[m] * scale;
            if (hasv1) out[(v0+1)*d + m] = acc1[m] * scale;
        }
    }
}

// ============ kernel D: out[r,i] = sum_j A[r,j] * ico[i,j] ============
// BLK_R=64, 64 padded cols; 256 threads; thread tile 4x4; A==nullptr -> g_TJ
__global__ __launch_bounds__(256) void kD(const float* __restrict__ A,
                                          const float* __restrict__ ico,
                                          float* __restrict__ out, int I) {
    __shared__ float As[32][68];   // [jj][r], padded
    __shared__ float Bs[32][64];   // [jj][i]
    const float* Ap = A ? A : g_TJ;
    const int r0 = blockIdx.x * 64;
    const int tid = threadIdx.x;
    const int tr = (tid & 15) * 4;
    const int tc = (tid >> 4) * 4;
    float acc[4][4];
    #pragma unroll
    for (int i = 0; i < 4; i++)
        #pragma unroll
        for (int j = 0; j < 4; j++) acc[i][j] = 0.f;

    for (int j0 = 0; j0 < DIM6c; j0 += 32) {
        int jrem = DIM6c - j0; if (jrem > 32) jrem = 32;
        #pragma unroll
        for (int i = 0; i < 8; i++) {
            int idx = tid + i*256;
            int jj = idx & 31, r = idx >> 5;
            As[jj][r] = (jj < jrem) ? Ap[(size_t)(r0 + r)*DIM6c + j0 + jj] : 0.f;
        }
        #pragma unroll
        for (int i = 0; i < 8; i++) {
            int idx = tid + i*256;
            int jj = idx & 31, ii = idx >> 5;
            Bs[jj][ii] = (ii < I && jj < jrem) ? ico[(size_t)ii*DIM6c + j0 + jj] : 0.f;
        }
        __syncthreads();
        #pragma unroll
        for (int jj = 0; jj < 32; jj++) {
            float4 a = *(const float4*)&As[jj][tr];
            float4 b = *(const float4*)&Bs[jj][tc];
            float av[4] = {a.x,a.y,a.z,a.w};
            float bv[4] = {b.x,b.y,b.z,b.w};
            #pragma unroll
            for (int i = 0; i < 4; i++)
                #pragma unroll
                for (int j = 0; j < 4; j++)
                    acc[i][j] += av[i] * bv[j];
        }
        __syncthreads();
    }
    #pragma unroll
    for (int i = 0; i < 4; i++) {
        #pragma unroll
        for (int j = 0; j < 4; j++) {
            int c = tc + j;
            if (c < I) out[(size_t)(r0 + tr + i)*I + c] = acc[i][j];
        }
    }
}

extern "C" void kernel_launch(void* const* d_in, const int* in_sizes, int n_in,
                              void* d_out, int out_size) {
    const float *x = nullptr, *traj = nullptr, *w1s = nullptr, *w1v = nullptr;
    const float *Din = nullptr, *Dout = nullptr, *ico = nullptr;
    const float* w2[7] = {};
    int icoN = 60;

    for (int i = 0; i < n_in; i++) {
        int sz = in_sizes[i];
        const float* p = (const float*)d_in[i];
        switch (sz) {
            case 7454720: x    = p; break;                 // x (32,4,128,455)
            case 5120:    traj = p; break;                 // trajectory (32,16,10)
            case 16:      w1s  = p; break;
            case 144:     w1v  = p; break;
            case 40960:   Din  = p; break;                 // (4096,10)
            case 1863680: Dout = p; break;                 // (4096,455)
            case 1024:    w2[0] = p; break;
            case 9216:    w2[1] = p; break;
            case 25600:   w2[2] = p; break;
            case 50176:   w2[3] = p; break;
            case 82944:   w2[4] = p; break;
            case 123904:  w2[5] = p; break;
            case 173056:  w2[6] = p; break;
            default:      ico = p; icoN = sz / DIM6c; break; // ico_wigners (I,455)
        }
    }
    float* out = (float*)d_out;

    kH<<<MROWS/256, 256>>>(traj, w1s, w1v);

    dim3 gB(MROWS/64, (DIM6c + 127)/128);
    kB<<<gB, 256>>>(Din, Dout);

    kC<0,0  ><<<BTc, 256>>>(w2[0]);
    kC<1,1  ><<<BTc, 256>>>(w2[1]);
    kC<2,10 ><<<BTc, 256>>>(w2[2]);
    kC<3,35 ><<<BTc, 256>>>(w2[3]);
    kC<4,84 ><<<BTc, 256>>>(w2[4]);
    kC<5,165><<<BTc, 256>>>(w2[5]);
    kC<6,286><<<BTc, 256>>>(w2[6]);

    // xg = x @ ico^T   (16384 rows), then traj_out = g_TJ @ ico^T (32768 rows)
    kD<<<XROWS/64, 256>>>(x, ico, out, icoN);
    kD<<<TROWS/64, 256>>>(nullptr, ico, out + (size_t)XROWS * icoN, icoN);
}

// round 2
// speedup vs baseline: 1.0983x; 1.0983x over previous
#include <cuda_runtime.h>
#include <math.h>

#define F8c   16
#define F2c   64
#define DIM6c 455
#define Gc    4096
#define MROWS 8192     // B*T*F8
#define BTc   512      // B*T
#define XROWS 16384    // B*H*C
#define TROWS 32768    // B*T*F2

// packed f32x2 helpers (sm_100+)
#define FMA2(acc, a, b) asm("fma.rn.f32x2 %0, %1, %2, %0;" : "+l"(acc) : "l"(a), "l"(b))
#define PACK2(dst, r)   asm("mov.b64 %0, {%1, %1};" : "=l"(dst) : "r"(r))

// -------- scratch --------
__device__ float g_H [MROWS * 10];
__device__ float g_HH[MROWS * DIM6c];
__device__ float g_TJ[BTc * F2c * DIM6c];

// ================= kernel H =================
__global__ void kH(const float* __restrict__ traj,
                   const float* __restrict__ w1s,
                   const float* __restrict__ w1v) {
    int row = blockIdx.x * blockDim.x + threadIdx.x;
    if (row >= MROWS) return;
    int bt = row >> 4, c = row & 15;
    const float* tr = traj + bt * 10;
    float tv[9];
    #pragma unroll
    for (int q = 0; q < 9; q++) tv[q] = tr[q];
    float s = tr[9];
    float* out = g_H + row * 10;
    out[0] = s * w1s[c];
    const float inv3 = 0.57735026918962576f;
    #pragma unroll
    for (int v = 0; v < 3; v++) {
        #pragma unroll
        for (int m = 0; m < 3; m++) {
            float a = 0.f;
            #pragma unroll
            for (int u = 0; u < 3; u++)
                a += tv[u*3 + m] * w1v[c*9 + u*3 + v];
            out[1 + v*3 + m] = a * inv3;
        }
    }
}

// ============ kernel B: HH = relu(H @ Din^T) @ Dout  (8192x4096x455) ============
// BLK_M=64, BLK_N=128, BLK_K=32; 256 threads; thread tile 4x8 with f32x2 FMAs
__global__ __launch_bounds__(256) void kB(const float* __restrict__ Din,
                                          const float* __restrict__ Dout) {
    __shared__ float Hs[64][10];
    __shared__ float sig_s[32][68];
    __shared__ float dout_s[32][128];

    const int m0 = blockIdx.x * 64;
    const int n0 = blockIdx.y * 128;
    const int tid = threadIdx.x;

    for (int i = tid; i < 64*10; i += 256)
        Hs[i/10][i%10] = g_H[m0*10 + i];
    __syncthreads();

    unsigned long long acc2[4][4];
    #pragma unroll
    for (int i = 0; i < 4; i++)
        #pragma unroll
        for (int j = 0; j < 4; j++) acc2[i][j] = 0ull;

    const int tm = (tid & 15) * 4;
    const int tn = (tid >> 4) * 8;

    for (int k0 = 0; k0 < Gc; k0 += 32) {
        // stage Dout chunk [32 x 128]
        #pragma unroll
        for (int i = 0; i < 16; i++) {
            int idx = tid + i*256;
            int kk = idx >> 7, n = idx & 127;
            int gn = n0 + n;
            dout_s[kk][n] = (gn < DIM6c) ? Dout[(size_t)(k0+kk)*DIM6c + gn] : 0.f;
        }
        // compute sig chunk [32 x 64]
        {
            int kk = tid >> 3;
            int mb = (tid & 7) * 8;
            float dr[10];
            #pragma unroll
            for (int q = 0; q < 10; q++) dr[q] = Din[(k0+kk)*10 + q];
            #pragma unroll
            for (int j = 0; j < 8; j++) {
                int m = mb + j;
                float a = 0.f;
                #pragma unroll
                for (int q = 0; q < 10; q++) a += Hs[m][q] * dr[q];
                sig_s[kk][m] = fmaxf(a, 0.f);
            }
        }
        __syncthreads();
        #pragma unroll
        for (int kk = 0; kk < 32; kk++) {
            float4 a4 = *(const float4*)&sig_s[kk][tm];
            unsigned long long ap[4];
            PACK2(ap[0], __float_as_uint(a4.x));
            PACK2(ap[1], __float_as_uint(a4.y));
            PACK2(ap[2], __float_as_uint(a4.z));
            PACK2(ap[3], __float_as_uint(a4.w));
            const ulonglong2* bp2 = (const ulonglong2*)&dout_s[kk][tn];
            ulonglong2 b01 = bp2[0], b23 = bp2[1];
            unsigned long long bp[4] = {b01.x, b01.y, b23.x, b23.y};
            #pragma unroll
            for (int i = 0; i < 4; i++)
                #pragma unroll
                for (int j = 0; j < 4; j++)
                    FMA2(acc2[i][j], ap[i], bp[j]);
        }
        __syncthreads();
    }
    #pragma unroll
    for (int i = 0; i < 4; i++) {
        #pragma unroll
        for (int j = 0; j < 4; j++) {
            unsigned int lo = (unsigned int)(acc2[i][j] & 0xFFFFFFFFull);
            unsigned int hi = (unsigned int)(acc2[i][j] >> 32);
            int gn0 = n0 + tn + 2*j;
            size_t rb = (size_t)(m0 + tm + i) * DIM6c;
            if (gn0 < DIM6c)     g_HH[rb + gn0]     = __uint_as_float(lo);
            if (gn0 + 1 < DIM6c) g_HH[rb + gn0 + 1] = __uint_as_float(hi);
        }
    }
}

// ============ kernel C (merged): per-l equi_linear with w2 ============
template<int L, int OFF>
__device__ __forceinline__ void kC_body(const float* __restrict__ w2, float* HHs) {
    constexpr int d  = 2*L + 1;
    constexpr int d2 = d * d;
    constexpr int PAIRS = (d + 1) / 2;
    const int bt = blockIdx.x;

    // load only the 16 x d^2 slice
    for (int i = threadIdx.x; i < F8c * d2; i += 256) {
        int f = i / d2, r = i - f * d2;
        HHs[f*d2 + r] = g_HH[(size_t)bt * F8c * DIM6c + f*DIM6c + OFF + r];
    }
    __syncthreads();

    const float scale = 0.25f * rsqrtf((float)d);

    for (int idx = threadIdx.x; idx < 64 * PAIRS; idx += 256) {
        int g2 = idx / PAIRS;
        int vp = idx - g2 * PAIRS;
        int v0 = vp * 2;
        const bool hasv1 = (v0 + 1 < d);
        float acc0[d], acc1[d];
        #pragma unroll
        for (int m = 0; m < d; m++) { acc0[m] = 0.f; acc1[m] = 0.f; }

        for (int f = 0; f < F8c; f++) {
            const float* wb = w2 + ((size_t)(f*64 + g2) * d) * d;
            const float* hb = HHs + f*d2;
            #pragma unroll
            for (int u = 0; u < d; u++) {
                float w0 = wb[u*d + v0];
                float w1 = hasv1 ? wb[u*d + v0 + 1] : 0.f;
                #pragma unroll
                for (int m = 0; m < d; m++) {
                    float h = hb[u*d + m];
                    acc0[m] += h * w0;
                    acc1[m] += h * w1;
                }
            }
        }
        float* out = g_TJ + ((size_t)(bt*64 + g2)) * DIM6c + OFF;
        #pragma unroll
        for (int m = 0; m < d; m++) {
            out[v0*d + m] = acc0[m] * scale;
            if (hasv1) out[(v0+1)*d + m] = acc1[m] * scale;
        }
    }
}

__global__ __launch_bounds__(256) void kCall(
    const float* w0, const float* w1, const float* w2p, const float* w3,
    const float* w4, const float* w5, const float* w6) {
    __shared__ float HHs[F8c * 169];   // max d^2 = 169 -> 10.8 KB
    switch (blockIdx.y) {
        case 0: kC_body<0,0  >(w0,  HHs); break;
        case 1: kC_body<1,1  >(w1,  HHs); break;
        case 2: kC_body<2,10 >(w2p, HHs); break;
        case 3: kC_body<3,35 >(w3,  HHs); break;
        case 4: kC_body<4,84 >(w4,  HHs); break;
        case 5: kC_body<5,165>(w5,  HHs); break;
        case 6: kC_body<6,286>(w6,  HHs); break;
    }
}

// ============ kernel D: out[r,i] = sum_j A[r,j] * ico[i,j] ============
__global__ __launch_bounds__(256) void kD(const float* __restrict__ A,
                                          const float* __restrict__ ico,
                                          float* __restrict__ out, int I) {
    __shared__ float As[32][68];
    __shared__ float Bs[32][64];
    const float* Ap = A ? A : g_TJ;
    const int r0 = blockIdx.x * 64;
    const int tid = threadIdx.x;
    const int tr = (tid & 15) * 4;
    const int tc = (tid >> 4) * 4;
    unsigned long long acc2[4][2];
    #pragma unroll
    for (int i = 0; i < 4; i++) { acc2[i][0] = 0ull; acc2[i][1] = 0ull; }

    for (int j0 = 0; j0 < DIM6c; j0 += 32) {
        int jrem = DIM6c - j0; if (jrem > 32) jrem = 32;
        #pragma unroll
        for (int i = 0; i < 8; i++) {
            int idx = tid + i*256;
            int jj = idx & 31, r = idx >> 5;
            As[jj][r] = (jj < jrem) ? Ap[(size_t)(r0 + r)*DIM6c + j0 + jj] : 0.f;
        }
        #pragma unroll
        for (int i = 0; i < 8; i++) {
            int idx = tid + i*256;
            int jj = idx & 31, ii = idx >> 5;
            Bs[jj][ii] = (ii < I && jj < jrem) ? ico[(size_t)ii*DIM6c + j0 + jj] : 0.f;
        }
        __syncthreads();
        #pragma unroll
        for (int jj = 0; jj < 32; jj++) {
            float4 a = *(const float4*)&As[jj][tr];
            unsigned long long ap[4];
            PACK2(ap[0], __float_as_uint(a.x));
            PACK2(ap[1], __float_as_uint(a.y));
            PACK2(ap[2], __float_as_uint(a.z));
            PACK2(ap[3], __float_as_uint(a.w));
            ulonglong2 b2 = *(const ulonglong2*)&Bs[jj][tc];
            unsigned long long bp[2] = {b2.x, b2.y};
            #pragma unroll
            for (int i = 0; i < 4; i++) {
                FMA2(acc2[i][0], ap[i], bp[0]);
                FMA2(acc2[i][1], ap[i], bp[1]);
            }
        }
        __syncthreads();
    }
    #pragma unroll
    for (int i = 0; i < 4; i++) {
        #pragma unroll
        for (int j = 0; j < 2; j++) {
            unsigned int lo = (unsigned int)(acc2[i][j] & 0xFFFFFFFFull);
            unsigned int hi = (unsigned int)(acc2[i][j] >> 32);
            int c0 = tc + 2*j;
            size_t rb = (size_t)(r0 + tr + i) * I;
            if (c0 < I)     out[rb + c0]     = __uint_as_float(lo);
            if (c0 + 1 < I) out[rb + c0 + 1] = __uint_as_float(hi);
        }
    }
}

extern "C" void kernel_launch(void* const* d_in, const int* in_sizes, int n_in,
                              void* d_out, int out_size) {
    const float *x = nullptr, *traj = nullptr, *w1s = nullptr, *w1v = nullptr;
    const float *Din = nullptr, *Dout = nullptr, *ico = nullptr;
    const float* w2[7] = {};
    int icoN = 60;

    for (int i = 0; i < n_in; i++) {
        int sz = in_sizes[i];
        const float* p = (const float*)d_in[i];
        switch (sz) {
            case 7454720: x    = p; break;
            case 5120:    traj = p; break;
            case 16:      w1s  = p; break;
            case 144:     w1v  = p; break;
            case 40960:   Din  = p; break;
            case 1863680: Dout = p; break;
            case 1024:    w2[0] = p; break;
            case 9216:    w2[1] = p; break;
            case 25600:   w2[2] = p; break;
            case 50176:   w2[3] = p; break;
            case 82944:   w2[4] = p; break;
            case 123904:  w2[5] = p; break;
            case 173056:  w2[6] = p; break;
            default:      ico = p; icoN = sz / DIM6c; break;
        }
    }
    float* out = (float*)d_out;

    kH<<<MROWS/256, 256>>>(traj, w1s, w1v);

    dim3 gB(MROWS/64, (DIM6c + 127)/128);
    kB<<<gB, 256>>>(Din, Dout);

    kCall<<<dim3(BTc, 7), 256>>>(w2[0], w2[1], w2[2], w2[3], w2[4], w2[5], w2[6]);

    kD<<<XROWS/64, 256>>>(x, ico, out, icoN);
    kD<<<TROWS/64, 256>>>(nullptr, ico, out + (size_t)XROWS * icoN, icoN);
}

// round 3
// speedup vs baseline: 1.9420x; 1.7683x over previous
#include <cuda_runtime.h>
#include <math.h>

#define F8c   16
#define F2c   64
#define DIM6c 455
#define Gc    4096
#define MROWS 8192     // B*T*F8
#define BTc   512      // B*T
#define XROWS 16384    // B*H*C
#define TROWS 32768    // B*T*F2
#define NPAD  512

// packed f32x2 helpers (sm_100+)
#define FMA2(acc, a, b) asm("fma.rn.f32x2 %0, %1, %2, %0;" : "+l"(acc) : "l"(a), "l"(b))
#define PACK2(dst, r)   asm("mov.b64 %0, {%1, %1};" : "=l"(dst) : "r"(r))

__device__ __forceinline__ unsigned int f2tf32(float f) {
    unsigned int r;
    asm("cvt.rna.tf32.f32 %0, %1;" : "=r"(r) : "f"(f));
    return r;
}

// -------- scratch --------
__device__ float        g_H [MROWS * 10];
__device__ unsigned int g_sig[(size_t)MROWS * Gc];     // tf32-rounded sig, 134MB
__device__ unsigned int g_DT [(size_t)Gc * NPAD];      // tf32-rounded Dout, padded
__device__ float        g_HH[MROWS * DIM6c];
__device__ float        g_TJ[BTc * F2c * DIM6c];

// ================= kernel H =================
__global__ void kH(const float* __restrict__ traj,
                   const float* __restrict__ w1s,
                   const float* __restrict__ w1v) {
    int row = blockIdx.x * blockDim.x + threadIdx.x;
    if (row >= MROWS) return;
    int bt = row >> 4, c = row & 15;
    const float* tr = traj + bt * 10;
    float tv[9];
    #pragma unroll
    for (int q = 0; q < 9; q++) tv[q] = tr[q];
    float s = tr[9];
    float* out = g_H + row * 10;
    out[0] = s * w1s[c];
    const float inv3 = 0.57735026918962576f;
    #pragma unroll
    for (int v = 0; v < 3; v++) {
        #pragma unroll
        for (int m = 0; m < 3; m++) {
            float a = 0.f;
            #pragma unroll
            for (int u = 0; u < 3; u++)
                a += tv[u*3 + m] * w1v[c*9 + u*3 + v];
            out[1 + v*3 + m] = a * inv3;
        }
    }
}

// ============ kSig: sig[m][k] = tf32(relu(H[m] . Din[k])) ============
// CTA: 32 m-rows x 256 k-cols. thread = one k; loops m. coalesced writes.
__global__ __launch_bounds__(256) void kSig(const float* __restrict__ Din) {
    __shared__ float Hs[32][10];
    const int m0 = blockIdx.y * 32;
    const int k  = blockIdx.x * 256 + threadIdx.x;
    for (int i = threadIdx.x; i < 320; i += 256)
        Hs[i/10][i%10] = g_H[m0*10 + i];
    __syncthreads();
    float dr[10];
    #pragma unroll
    for (int q = 0; q < 10; q++) dr[q] = Din[k*10 + q];
    #pragma unroll 4
    for (int m = 0; m < 32; m++) {
        float a = 0.f;
        #pragma unroll
        for (int q = 0; q < 10; q++) a += Hs[m][q] * dr[q];
        g_sig[(size_t)(m0 + m) * Gc + k] = f2tf32(fmaxf(a, 0.f));
    }
}

// ============ kCvt: DoutT padded tf32 copy ============
__global__ void kCvt(const float* __restrict__ Dout) {
    int idx = blockIdx.x * blockDim.x + threadIdx.x;   // over Gc*NPAD
    int k = idx >> 9, n = idx & (NPAD - 1);
    g_DT[idx] = (n < DIM6c) ? f2tf32(Dout[(size_t)k * DIM6c + n]) : 0u;
}

// ============ kBmma: g_HH = sig @ DoutT via tf32 mma.sync ============
// BM=128, BN=128, BK=32; 8 warps (4x2), warp tile 32x64, thread frags m16n8k8.
#define SSTR 132
__global__ __launch_bounds__(256) void kBmma() {
    __shared__ unsigned int As[32][SSTR];   // [k][m]
    __shared__ unsigned int Bs[32][SSTR];   // [k][n]
    const int n0 = blockIdx.x * 128;
    const int m0 = blockIdx.y * 128;
    const int tid = threadIdx.x;
    const int wid = tid >> 5, lane = tid & 31;
    const int wm = wid >> 1, wn = wid & 1;
    const int lr = lane >> 2;        // 0..7
    const int lc = lane & 3;         // 0..3

    float acc[2][8][4];
    #pragma unroll
    for (int mi = 0; mi < 2; mi++)
        #pragma unroll
        for (int nj = 0; nj < 8; nj++)
            #pragma unroll
            for (int r = 0; r < 4; r++) acc[mi][nj][r] = 0.f;

    const int a_m = tid >> 1;              // 0..127
    const int a_k = (tid & 1) * 16;        // 0 or 16
    const int b_k = tid >> 3;              // 0..31
    const int b_n = (tid & 7) * 16;        // 0..112

    for (int k0 = 0; k0 < Gc; k0 += 32) {
        // load A chunk [128 m][32 k] -> As[k][m]
        {
            const uint4* src = (const uint4*)(g_sig + (size_t)(m0 + a_m) * Gc + k0 + a_k);
            uint4 v[4];
            #pragma unroll
            for (int j = 0; j < 4; j++) v[j] = src[j];
            #pragma unroll
            for (int j = 0; j < 4; j++) {
                As[a_k + 4*j + 0][a_m] = v[j].x;
                As[a_k + 4*j + 1][a_m] = v[j].y;
                As[a_k + 4*j + 2][a_m] = v[j].z;
                As[a_k + 4*j + 3][a_m] = v[j].w;
            }
        }
        // load B chunk [32 k][128 n] -> Bs[k][n]
        {
            const uint4* src = (const uint4*)(g_DT + (size_t)(k0 + b_k) * NPAD + n0 + b_n);
            #pragma unroll
            for (int j = 0; j < 4; j++)
                *(uint4*)&Bs[b_k][b_n + 4*j] = src[j];
        }
        __syncthreads();

        #pragma unroll
        for (int kc = 0; kc < 4; kc++) {
            const int kb = kc * 8;
            unsigned int afr[2][4];
            #pragma unroll
            for (int mi = 0; mi < 2; mi++) {
                int rb = wm*32 + mi*16 + lr;
                afr[mi][0] = As[kb + lc    ][rb    ];
                afr[mi][1] = As[kb + lc    ][rb + 8];
                afr[mi][2] = As[kb + lc + 4][rb    ];
                afr[mi][3] = As[kb + lc + 4][rb + 8];
            }
            #pragma unroll
            for (int nj = 0; nj < 8; nj++) {
                int nb = wn*64 + nj*8 + lr;
                unsigned int b0 = Bs[kb + lc    ][nb];
                unsigned int b1 = Bs[kb + lc + 4][nb];
                #pragma unroll
                for (int mi = 0; mi < 2; mi++) {
                    asm volatile(
                        "mma.sync.aligned.m16n8k8.row.col.f32.tf32.tf32.f32 "
                        "{%0,%1,%2,%3}, {%4,%5,%6,%7}, {%8,%9}, {%0,%1,%2,%3};"
                        : "+f"(acc[mi][nj][0]), "+f"(acc[mi][nj][1]),
                          "+f"(acc[mi][nj][2]), "+f"(acc[mi][nj][3])
                        : "r"(afr[mi][0]), "r"(afr[mi][1]),
                          "r"(afr[mi][2]), "r"(afr[mi][3]),
                          "r"(b0), "r"(b1));
                }
            }
        }
        __syncthreads();
    }

    // epilogue
    #pragma unroll
    for (int mi = 0; mi < 2; mi++) {
        #pragma unroll
        for (int nj = 0; nj < 8; nj++) {
            int row = m0 + wm*32 + mi*16 + lr;
            int col = n0 + wn*64 + nj*8 + lc*2;
            if (col < DIM6c) {
                g_HH[(size_t)row * DIM6c + col] = acc[mi][nj][0];
                if (col + 1 < DIM6c) g_HH[(size_t)row * DIM6c + col + 1] = acc[mi][nj][1];
                g_HH[(size_t)(row + 8) * DIM6c + col] = acc[mi][nj][2];
                if (col + 1 < DIM6c) g_HH[(size_t)(row + 8) * DIM6c + col + 1] = acc[mi][nj][3];
            }
        }
    }
}

// ============ kernel C (merged): per-l equi_linear with w2 ============
template<int L, int OFF>
__device__ __forceinline__ void kC_body(const float* __restrict__ w2, float* HHs) {
    constexpr int d  = 2*L + 1;
    constexpr int d2 = d * d;
    constexpr int PAIRS = (d + 1) / 2;
    const int bt = blockIdx.x;

    for (int i = threadIdx.x; i < F8c * d2; i += 256) {
        int f = i / d2, r = i - f * d2;
        HHs[f*d2 + r] = g_HH[(size_t)bt * F8c * DIM6c + f*DIM6c + OFF + r];
    }
    __syncthreads();

    const float scale = 0.25f * rsqrtf((float)d);

    for (int idx = threadIdx.x; idx < 64 * PAIRS; idx += 256) {
        int g2 = idx / PAIRS;
        int vp = idx - g2 * PAIRS;
        int v0 = vp * 2;
        const bool hasv1 = (v0 + 1 < d);
        float acc0[d], acc1[d];
        #pragma unroll
        for (int m = 0; m < d; m++) { acc0[m] = 0.f; acc1[m] = 0.f; }

        for (int f = 0; f < F8c; f++) {
            const float* wb = w2 + ((size_t)(f*64 + g2) * d) * d;
            const float* hb = HHs + f*d2;
            #pragma unroll
            for (int u = 0; u < d; u++) {
                float w0 = wb[u*d + v0];
                float w1 = hasv1 ? wb[u*d + v0 + 1] : 0.f;
                #pragma unroll
                for (int m = 0; m < d; m++) {
                    float h = hb[u*d + m];
                    acc0[m] += h * w0;
                    acc1[m] += h * w1;
                }
            }
        }
        float* out = g_TJ + ((size_t)(bt*64 + g2)) * DIM6c + OFF;
        #pragma unroll
        for (int m = 0; m < d; m++) {
            out[v0*d + m] = acc0[m] * scale;
            if (hasv1) out[(v0+1)*d + m] = acc1[m] * scale;
        }
    }
}

__global__ __launch_bounds__(256) void kCall(
    const float* w0, const float* w1, const float* w2p, const float* w3,
    const float* w4, const float* w5, const float* w6) {
    __shared__ float HHs[F8c * 169];
    switch (blockIdx.y) {
        case 0: kC_body<0,0  >(w0,  HHs); break;
        case 1: kC_body<1,1  >(w1,  HHs); break;
        case 2: kC_body<2,10 >(w2p, HHs); break;
        case 3: kC_body<3,35 >(w3,  HHs); break;
        case 4: kC_body<4,84 >(w4,  HHs); break;
        case 5: kC_body<5,165>(w5,  HHs); break;
        case 6: kC_body<6,286>(w6,  HHs); break;
    }
}

// ============ kernel D: out[r,i] = sum_j A[r,j] * ico[i,j] ============
__global__ __launch_bounds__(256) void kD(const float* __restrict__ A,
                                          const float* __restrict__ ico,
                                          float* __restrict__ out, int I) {
    __shared__ float As[32][68];
    __shared__ float Bs[32][64];
    const float* Ap = A ? A : g_TJ;
    const int r0 = blockIdx.x * 64;
    const int tid = threadIdx.x;
    const int tr = (tid & 15) * 4;
    const int tc = (tid >> 4) * 4;
    unsigned long long acc2[4][2];
    #pragma unroll
    for (int i = 0; i < 4; i++) { acc2[i][0] = 0ull; acc2[i][1] = 0ull; }

    for (int j0 = 0; j0 < DIM6c; j0 += 32) {
        int jrem = DIM6c - j0; if (jrem > 32) jrem = 32;
        #pragma unroll
        for (int i = 0; i < 8; i++) {
            int idx = tid + i*256;
            int jj = idx & 31, r = idx >> 5;
            As[jj][r] = (jj < jrem) ? Ap[(size_t)(r0 + r)*DIM6c + j0 + jj] : 0.f;
        }
        #pragma unroll
        for (int i = 0; i < 8; i++) {
            int idx = tid + i*256;
            int jj = idx & 31, ii = idx >> 5;
            Bs[jj][ii] = (ii < I && jj < jrem) ? ico[(size_t)ii*DIM6c + j0 + jj] : 0.f;
        }
        __syncthreads();
        #pragma unroll
        for (int jj = 0; jj < 32; jj++) {
            float4 a = *(const float4*)&As[jj][tr];
            unsigned long long ap[4];
            PACK2(ap[0], __float_as_uint(a.x));
            PACK2(ap[1], __float_as_uint(a.y));
            PACK2(ap[2], __float_as_uint(a.z));
            PACK2(ap[3], __float_as_uint(a.w));
            ulonglong2 b2 = *(const ulonglong2*)&Bs[jj][tc];
            unsigned long long bp[2] = {b2.x, b2.y};
            #pragma unroll
            for (int i = 0; i < 4; i++) {
                FMA2(acc2[i][0], ap[i], bp[0]);
                FMA2(acc2[i][1], ap[i], bp[1]);
            }
        }
        __syncthreads();
    }
    #pragma unroll
    for (int i = 0; i < 4; i++) {
        #pragma unroll
        for (int j = 0; j < 2; j++) {
            unsigned int lo = (unsigned int)(acc2[i][j] & 0xFFFFFFFFull);
            unsigned int hi = (unsigned int)(acc2[i][j] >> 32);
            int c0 = tc + 2*j;
            size_t rb = (size_t)(r0 + tr + i) * I;
            if (c0 < I)     out[rb + c0]     = __uint_as_float(lo);
            if (c0 + 1 < I) out[rb + c0 + 1] = __uint_as_float(hi);
        }
    }
}

extern "C" void kernel_launch(void* const* d_in, const int* in_sizes, int n_in,
                              void* d_out, int out_size) {
    const float *x = nullptr, *traj = nullptr, *w1s = nullptr, *w1v = nullptr;
    const float *Din = nullptr, *Dout = nullptr, *ico = nullptr;
    const float* w2[7] = {};
    int icoN = 60;

    for (int i = 0; i < n_in; i++) {
        int sz = in_sizes[i];
        const float* p = (const float*)d_in[i];
        switch (sz) {
            case 7454720: x    = p; break;
            case 5120:    traj = p; break;
            case 16:      w1s  = p; break;
            case 144:     w1v  = p; break;
            case 40960:   Din  = p; break;
            case 1863680: Dout = p; break;
            case 1024:    w2[0] = p; break;
            case 9216:    w2[1] = p; break;
            case 25600:   w2[2] = p; break;
            case 50176:   w2[3] = p; break;
            case 82944:   w2[4] = p; break;
            case 123904:  w2[5] = p; break;
            case 173056:  w2[6] = p; break;
            default:      ico = p; icoN = sz / DIM6c; break;
        }
    }
    float* out = (float*)d_out;

    kH<<<MROWS/256, 256>>>(traj, w1s, w1v);
    kCvt<<<(Gc * NPAD) / 256, 256>>>(Dout);
    kSig<<<dim3(Gc/256, MROWS/32), 256>>>(Din);

    kBmma<<<dim3(4, MROWS/128), 256>>>();

    kCall<<<dim3(BTc, 7), 256>>>(w2[0], w2[1], w2[2], w2[3], w2[4], w2[5], w2[6]);

    kD<<<XROWS/64, 256>>>(x, ico, out, icoN);
    kD<<<TROWS/64, 256>>>(nullptr, ico, out + (size_t)XROWS * icoN, icoN);
}

// round 4
// speedup vs baseline: 3.1394x; 1.6166x over previous
#include <cuda_runtime.h>
#include <math.h>

#define F8c   16
#define F2c   64
#define DIM6c 455
#define Gc    4096
#define MROWS 8192     // B*T*F8
#define BTc   512      // B*T
#define XROWS 16384    // B*H*C
#define TROWS 32768    // B*T*F2
#define NPAD  512

__device__ __forceinline__ unsigned int f2tf32(float f) {
    unsigned int r;
    asm("cvt.rna.tf32.f32 %0, %1;" : "=r"(r) : "f"(f));
    return r;
}

__device__ __forceinline__ unsigned int smem_u32(const void* p) {
    return (unsigned int)__cvta_generic_to_shared(p);
}
#define CP_ASYNC16(dst, src) \
    asm volatile("cp.async.cg.shared.global [%0], [%1], 16;" :: "r"(dst), "l"(src))
#define CP_COMMIT()  asm volatile("cp.async.commit_group;")
#define CP_WAIT1()   asm volatile("cp.async.wait_group 1;")

#define MMA_TF32(c0,c1,c2,c3,a0,a1,a2,a3,b0,b1) \
    asm volatile("mma.sync.aligned.m16n8k8.row.col.f32.tf32.tf32.f32 " \
        "{%0,%1,%2,%3}, {%4,%5,%6,%7}, {%8,%9}, {%0,%1,%2,%3};" \
        : "+f"(c0), "+f"(c1), "+f"(c2), "+f"(c3) \
        : "r"(a0), "r"(a1), "r"(a2), "r"(a3), "r"(b0), "r"(b1))

// -------- scratch --------
__device__ float        g_H  [MROWS * 10];
__device__ unsigned int g_sigT[(size_t)Gc * MROWS];    // tf32 sig, [k][m], 134MB
__device__ unsigned int g_DT [(size_t)Gc * NPAD];      // tf32 Dout, [k][n] padded
__device__ float        g_HH[MROWS * DIM6c];
__device__ float        g_TJ[BTc * F2c * DIM6c];

// ================= kernel H =================
__global__ void kH(const float* __restrict__ traj,
                   const float* __restrict__ w1s,
                   const float* __restrict__ w1v) {
    int row = blockIdx.x * blockDim.x + threadIdx.x;
    if (row >= MROWS) return;
    int bt = row >> 4, c = row & 15;
    const float* tr = traj + bt * 10;
    float tv[9];
    #pragma unroll
    for (int q = 0; q < 9; q++) tv[q] = tr[q];
    float s = tr[9];
    float* out = g_H + row * 10;
    out[0] = s * w1s[c];
    const float inv3 = 0.57735026918962576f;
    #pragma unroll
    for (int v = 0; v < 3; v++) {
        #pragma unroll
        for (int m = 0; m < 3; m++) {
            float a = 0.f;
            #pragma unroll
            for (int u = 0; u < 3; u++)
                a += tv[u*3 + m] * w1v[c*9 + u*3 + v];
            out[1 + v*3 + m] = a * inv3;
        }
    }
}

// ============ kSigT: g_sigT[k][m] = tf32(relu(H[m].Din[k])), coalesced on m ===
__global__ __launch_bounds__(256) void kSigT(const float* __restrict__ Din) {
    __shared__ float Ds[8][10];
    const int m  = blockIdx.x * 256 + threadIdx.x;
    const int k0 = blockIdx.y * 8;
    if (threadIdx.x < 80)
        Ds[threadIdx.x / 10][threadIdx.x % 10] = Din[k0*10 + threadIdx.x];
    __syncthreads();
    float h[10];
    #pragma unroll
    for (int q = 0; q < 10; q++) h[q] = g_H[m*10 + q];
    #pragma unroll
    for (int kk = 0; kk < 8; kk++) {
        float a = 0.f;
        #pragma unroll
        for (int q = 0; q < 10; q++) a += h[q] * Ds[kk][q];
        g_sigT[(size_t)(k0 + kk) * MROWS + m] = f2tf32(fmaxf(a, 0.f));
    }
}

// ============ kCvt: Dout padded tf32 copy ============
__global__ void kCvt(const float* __restrict__ Dout) {
    int idx = blockIdx.x * blockDim.x + threadIdx.x;
    int k = idx >> 9, n = idx & (NPAD - 1);
    g_DT[idx] = (n < DIM6c) ? f2tf32(Dout[(size_t)k * DIM6c + n]) : 0u;
}

// ============ kBmma: g_HH = sig @ Dout, tf32 mma, cp.async 2-stage =========
// BM=128, BN=128, BK=16, 2 kc-steps/stage; 8 warps (4x2), warp tile 32x64
#define SSTR 136
__global__ __launch_bounds__(256) void kBmma() {
    __shared__ unsigned int As[2][16][SSTR];   // [k][m]
    __shared__ unsigned int Bs[2][16][SSTR];   // [k][n]
    const int n0 = blockIdx.x * 128;
    const int m0 = blockIdx.y * 128;
    const int tid = threadIdx.x;
    const int wid = tid >> 5, lane = tid & 31;
    const int wm = wid >> 1, wn = wid & 1;
    const int lr = lane >> 2;        // 0..7
    const int lc = lane & 3;         // 0..3

    float acc[2][8][4];
    #pragma unroll
    for (int mi = 0; mi < 2; mi++)
        #pragma unroll
        for (int nj = 0; nj < 8; nj++)
            #pragma unroll
            for (int r = 0; r < 4; r++) acc[mi][nj][r] = 0.f;

    // cp.async mapping: 512 uint4 per array per stage, 2 per thread
    const int ld_row0 = tid >> 5;          // 0..7
    const int ld_row1 = ld_row0 + 8;
    const int ld_c4   = (tid & 31) * 4;    // 0..124

    auto issue = [&](int buf, int k0) {
        CP_ASYNC16(smem_u32(&As[buf][ld_row0][ld_c4]),
                   g_sigT + (size_t)(k0 + ld_row0) * MROWS + m0 + ld_c4);
        CP_ASYNC16(smem_u32(&As[buf][ld_row1][ld_c4]),
                   g_sigT + (size_t)(k0 + ld_row1) * MROWS + m0 + ld_c4);
        CP_ASYNC16(smem_u32(&Bs[buf][ld_row0][ld_c4]),
                   g_DT + (size_t)(k0 + ld_row0) * NPAD + n0 + ld_c4);
        CP_ASYNC16(smem_u32(&Bs[buf][ld_row1][ld_c4]),
                   g_DT + (size_t)(k0 + ld_row1) * NPAD + n0 + ld_c4);
    };

    issue(0, 0);  CP_COMMIT();
    issue(1, 16); CP_COMMIT();

    const int NIT = Gc / 16;  // 256
    for (int it = 0; it < NIT; it++) {
        const int buf = it & 1;
        CP_WAIT1();
        __syncthreads();

        #pragma unroll
        for (int kc = 0; kc < 2; kc++) {
            const int kb = kc * 8;
            unsigned int afr[2][4];
            #pragma unroll
            for (int mi = 0; mi < 2; mi++) {
                int rb = wm*32 + mi*16 + lr;
                afr[mi][0] = As[buf][kb + lc    ][rb    ];
                afr[mi][1] = As[buf][kb + lc    ][rb + 8];
                afr[mi][2] = As[buf][kb + lc + 4][rb    ];
                afr[mi][3] = As[buf][kb + lc + 4][rb + 8];
            }
            #pragma unroll
            for (int nj = 0; nj < 8; nj++) {
                int nb = wn*64 + nj*8 + lr;
                unsigned int b0 = Bs[buf][kb + lc    ][nb];
                unsigned int b1 = Bs[buf][kb + lc + 4][nb];
                #pragma unroll
                for (int mi = 0; mi < 2; mi++)
                    MMA_TF32(acc[mi][nj][0], acc[mi][nj][1], acc[mi][nj][2], acc[mi][nj][3],
                             afr[mi][0], afr[mi][1], afr[mi][2], afr[mi][3], b0, b1);
            }
        }
        __syncthreads();
        int nk = (it + 2) * 16;
        if (nk < Gc) issue(buf, nk);
        CP_COMMIT();
    }

    // epilogue
    #pragma unroll
    for (int mi = 0; mi < 2; mi++) {
        #pragma unroll
        for (int nj = 0; nj < 8; nj++) {
            int row = m0 + wm*32 + mi*16 + lr;
            int col = n0 + wn*64 + nj*8 + lc*2;
            if (col < DIM6c) {
                g_HH[(size_t)row * DIM6c + col] = acc[mi][nj][0];
                if (col + 1 < DIM6c) g_HH[(size_t)row * DIM6c + col + 1] = acc[mi][nj][1];
                g_HH[(size_t)(row + 8) * DIM6c + col] = acc[mi][nj][2];
                if (col + 1 < DIM6c) g_HH[(size_t)(row + 8) * DIM6c + col + 1] = acc[mi][nj][3];
            }
        }
    }
}

// ============ kernel C (merged): per-l equi_linear with w2 ============
template<int L, int OFF>
__device__ __forceinline__ void kC_body(const float* __restrict__ w2, float* HHs) {
    constexpr int d  = 2*L + 1;
    constexpr int d2 = d * d;
    constexpr int PAIRS = (d + 1) / 2;
    const int bt = blockIdx.x;

    for (int i = threadIdx.x; i < F8c * d2; i += 256) {
        int f = i / d2, r = i - f * d2;
        HHs[f*d2 + r] = g_HH[(size_t)bt * F8c * DIM6c + f*DIM6c + OFF + r];
    }
    __syncthreads();

    const float scale = 0.25f * rsqrtf((float)d);

    for (int idx = threadIdx.x; idx < 64 * PAIRS; idx += 256) {
        int g2 = idx / PAIRS;
        int vp = idx - g2 * PAIRS;
        int v0 = vp * 2;
        const bool hasv1 = (v0 + 1 < d);
        float acc0[d], acc1[d];
        #pragma unroll
        for (int m = 0; m < d; m++) { acc0[m] = 0.f; acc1[m] = 0.f; }

        for (int f = 0; f < F8c; f++) {
            const float* wb = w2 + ((size_t)(f*64 + g2) * d) * d;
            const float* hb = HHs + f*d2;
            #pragma unroll
            for (int u = 0; u < d; u++) {
                float w0 = wb[u*d + v0];
                float w1 = hasv1 ? wb[u*d + v0 + 1] : 0.f;
                #pragma unroll
                for (int m = 0; m < d; m++) {
                    float h = hb[u*d + m];
                    acc0[m] += h * w0;
                    acc1[m] += h * w1;
                }
            }
        }
        float* out = g_TJ + ((size_t)(bt*64 + g2)) * DIM6c + OFF;
        #pragma unroll
        for (int m = 0; m < d; m++) {
            out[v0*d + m] = acc0[m] * scale;
            if (hasv1) out[(v0+1)*d + m] = acc1[m] * scale;
        }
    }
}

__global__ __launch_bounds__(256) void kCall(
    const float* w0, const float* w1, const float* w2p, const float* w3,
    const float* w4, const float* w5, const float* w6) {
    __shared__ float HHs[F8c * 169];
    switch (blockIdx.y) {
        case 0: kC_body<0,0  >(w0,  HHs); break;
        case 1: kC_body<1,1  >(w1,  HHs); break;
        case 2: kC_body<2,10 >(w2p, HHs); break;
        case 3: kC_body<3,35 >(w3,  HHs); break;
        case 4: kC_body<4,84 >(w4,  HHs); break;
        case 5: kC_body<5,165>(w5,  HHs); break;
        case 6: kC_body<6,286>(w6,  HHs); break;
    }
}

// ============ kDmma: out[r][i] = sum_j A[r][j] * ico[i][j], tf32 mma ========
// merged over rows: r < XROWS -> x, else g_TJ. BM=128, BN=64, BK=32, 15 iters
__global__ __launch_bounds__(256) void kDmma(const float* __restrict__ x,
                                             const float* __restrict__ ico,
                                             float* __restrict__ out, int I) {
    __shared__ unsigned int As[128][36];   // [m][k]
    __shared__ unsigned int Bs[64][36];    // [n][k]
    const int r0 = blockIdx.x * 128;
    const float* Ap = (r0 < XROWS) ? (x + (size_t)r0 * DIM6c)
                                   : (g_TJ + (size_t)(r0 - XROWS) * DIM6c);
    const int tid = threadIdx.x;
    const int wid = tid >> 5, lane = tid & 31;
    const int wm = wid >> 1, wn = wid & 1;
    const int lr = lane >> 2;
    const int lc = lane & 3;

    float acc[2][4][4];
    #pragma unroll
    for (int mi = 0; mi < 2; mi++)
        #pragma unroll
        for (int nj = 0; nj < 4; nj++)
            #pragma unroll
            for (int r = 0; r < 4; r++) acc[mi][nj][r] = 0.f;

    for (int j0 = 0; j0 < 480; j0 += 32) {
        // A: 128 x 32, coalesced along k
        #pragma unroll
        for (int i = 0; i < 16; i++) {
            int idx = i*256 + tid;
            int r = idx >> 5, kk = idx & 31;
            int j = j0 + kk;
            As[r][kk] = (j < DIM6c) ? f2tf32(Ap[(size_t)r * DIM6c + j]) : 0u;
        }
        // B: 64 x 32
        #pragma unroll
        for (int i = 0; i < 8; i++) {
            int idx = i*256 + tid;
            int n = idx >> 5, kk = idx & 31;
            int j = j0 + kk;
            Bs[n][kk] = (n < I && j < DIM6c) ? f2tf32(ico[(size_t)n * DIM6c + j]) : 0u;
        }
        __syncthreads();

        #pragma unroll
        for (int kc = 0; kc < 4; kc++) {
            const int kb = kc * 8;
            unsigned int afr[2][4];
            #pragma unroll
            for (int mi = 0; mi < 2; mi++) {
                int rb = wm*32 + mi*16 + lr;
                afr[mi][0] = As[rb    ][kb + lc    ];
                afr[mi][1] = As[rb + 8][kb + lc    ];
                afr[mi][2] = As[rb    ][kb + lc + 4];
                afr[mi][3] = As[rb + 8][kb + lc + 4];
            }
            #pragma unroll
            for (int nj = 0; nj < 4; nj++) {
                int nb = wn*32 + nj*8 + lr;
                unsigned int b0 = Bs[nb][kb + lc    ];
                unsigned int b1 = Bs[nb][kb + lc + 4];
                #pragma unroll
                for (int mi = 0; mi < 2; mi++)
                    MMA_TF32(acc[mi][nj][0], acc[mi][nj][1], acc[mi][nj][2], acc[mi][nj][3],
                             afr[mi][0], afr[mi][1], afr[mi][2], afr[mi][3], b0, b1);
            }
        }
        __syncthreads();
    }

    #pragma unroll
    for (int mi = 0; mi < 2; mi++) {
        #pragma unroll
        for (int nj = 0; nj < 4; nj++) {
            int row = r0 + wm*32 + mi*16 + lr;
            int col = wn*32 + nj*8 + lc*2;
            if (col < I) {
                out[(size_t)row * I + col] = acc[mi][nj][0];
                out[(size_t)(row + 8) * I + col] = acc[mi][nj][2];
                if (col + 1 < I) {
                    out[(size_t)row * I + col + 1] = acc[mi][nj][1];
                    out[(size_t)(row + 8) * I + col + 1] = acc[mi][nj][3];
                }
            }
        }
    }
}

extern "C" void kernel_launch(void* const* d_in, const int* in_sizes, int n_in,
                              void* d_out, int out_size) {
    const float *x = nullptr, *traj = nullptr, *w1s = nullptr, *w1v = nullptr;
    const float *Din = nullptr, *Dout = nullptr, *ico = nullptr;
    const float* w2[7] = {};
    int icoN = 60;

    for (int i = 0; i < n_in; i++) {
        int sz = in_sizes[i];
        const float* p = (const float*)d_in[i];
        switch (sz) {
            case 7454720: x    = p; break;
            case 5120:    traj = p; break;
            case 16:      w1s  = p; break;
            case 144:     w1v  = p; break;
            case 40960:   Din  = p; break;
            case 1863680: Dout = p; break;
            case 1024:    w2[0] = p; break;
            case 9216:    w2[1] = p; break;
            case 25600:   w2[2] = p; break;
            case 50176:   w2[3] = p; break;
            case 82944:   w2[4] = p; break;
            case 123904:  w2[5] = p; break;
            case 173056:  w2[6] = p; break;
            default:      ico = p; icoN = sz / DIM6c; break;
        }
    }
    float* out = (float*)d_out;

    kH<<<MROWS/256, 256>>>(traj, w1s, w1v);
    kCvt<<<(Gc * NPAD) / 256, 256>>>(Dout);
    kSigT<<<dim3(MROWS/256, Gc/8), 256>>>(Din);

    kBmma<<<dim3(4, MROWS/128), 256>>>();

    kCall<<<dim3(BTc, 7), 256>>>(w2[0], w2[1], w2[2], w2[3], w2[4], w2[5], w2[6]);

    kDmma<<<(XROWS + TROWS)/128, 256>>>(x, ico, out, icoN);
}

// round 5
// speedup vs baseline: 5.0847x; 1.6196x over previous
#include <cuda_runtime.h>
#include <math.h>

#define F8c   16
#define F2c   64
#define DIM6c 455
#define Gc    4096
#define MROWS 8192     // B*T*F8
#define BTc   512      // B*T
#define XROWS 16384    // B*H*C
#define TROWS 32768    // B*T*F2
#define NPAD  512

__device__ __forceinline__ unsigned int f2tf32(float f) {
    unsigned int r;
    asm("cvt.rna.tf32.f32 %0, %1;" : "=r"(r) : "f"(f));
    return r;
}

__device__ __forceinline__ unsigned int smem_u32(const void* p) {
    return (unsigned int)__cvta_generic_to_shared(p);
}
#define CP_ASYNC16(dst, src) \
    asm volatile("cp.async.cg.shared.global [%0], [%1], 16;" :: "r"(dst), "l"(src))
#define CP_COMMIT()  asm volatile("cp.async.commit_group;")
#define CP_WAIT1()   asm volatile("cp.async.wait_group 1;")

#define MMA_TF32(c0,c1,c2,c3,a0,a1,a2,a3,b0,b1) \
    asm volatile("mma.sync.aligned.m16n8k8.row.col.f32.tf32.tf32.f32 " \
        "{%0,%1,%2,%3}, {%4,%5,%6,%7}, {%8,%9}, {%0,%1,%2,%3};" \
        : "+f"(c0), "+f"(c1), "+f"(c2), "+f"(c3) \
        : "r"(a0), "r"(a1), "r"(a2), "r"(a3), "r"(b0), "r"(b1))

// -------- scratch --------
__device__ float        g_H  [MROWS * 10];
__device__ unsigned int g_sigT[(size_t)Gc * MROWS];    // tf32 sig, [k][m]
__device__ unsigned int g_DT [(size_t)Gc * NPAD];      // tf32 Dout, [k][n]
__device__ float        g_HH[MROWS * DIM6c];
__device__ unsigned int g_A [8192 * 455];              // per-l A_l [(f*d+u)][(bt*d+m)]
__device__ unsigned int g_B [1024 * 455];              // per-l B_l [(f*d+u)][(g2*d+v)]
__device__ float        g_TJ[BTc * F2c * DIM6c];

// per-l cumulative bases (cum d^2 = 0,1,10,35,84,165,286)
#define AB0 0
#define AB1 (8192*1)
#define AB2 (8192*10)
#define AB3 (8192*35)
#define AB4 (8192*84)
#define AB5 (8192*165)
#define AB6 (8192*286)
#define BB0 0
#define BB1 (1024*1)
#define BB2 (1024*10)
#define BB3 (1024*35)
#define BB4 (1024*84)
#define BB5 (1024*165)
#define BB6 (1024*286)

// ================= kernel H =================
__global__ void kH(const float* __restrict__ traj,
                   const float* __restrict__ w1s,
                   const float* __restrict__ w1v) {
    int row = blockIdx.x * blockDim.x + threadIdx.x;
    if (row >= MROWS) return;
    int bt = row >> 4, c = row & 15;
    const float* tr = traj + bt * 10;
    float tv[9];
    #pragma unroll
    for (int q = 0; q < 9; q++) tv[q] = tr[q];
    float s = tr[9];
    float* out = g_H + row * 10;
    out[0] = s * w1s[c];
    const float inv3 = 0.57735026918962576f;
    #pragma unroll
    for (int v = 0; v < 3; v++) {
        #pragma unroll
        for (int m = 0; m < 3; m++) {
            float a = 0.f;
            #pragma unroll
            for (int u = 0; u < 3; u++)
                a += tv[u*3 + m] * w1v[c*9 + u*3 + v];
            out[1 + v*3 + m] = a * inv3;
        }
    }
}

// ============ kSigT: g_sigT[k][m] = tf32(relu(H[m].Din[k])) ============
__global__ __launch_bounds__(256) void kSigT(const float* __restrict__ Din) {
    __shared__ float Ds[8][10];
    const int m  = blockIdx.x * 256 + threadIdx.x;
    const int k0 = blockIdx.y * 8;
    if (threadIdx.x < 80)
        Ds[threadIdx.x / 10][threadIdx.x % 10] = Din[k0*10 + threadIdx.x];
    __syncthreads();
    float h[10];
    #pragma unroll
    for (int q = 0; q < 10; q++) h[q] = g_H[m*10 + q];
    #pragma unroll
    for (int kk = 0; kk < 8; kk++) {
        float a = 0.f;
        #pragma unroll
        for (int q = 0; q < 10; q++) a += h[q] * Ds[kk][q];
        g_sigT[(size_t)(k0 + kk) * MROWS + m] = f2tf32(fmaxf(a, 0.f));
    }
}

// ============ kCvt: Dout padded tf32 copy ============
__global__ void kCvt(const float* __restrict__ Dout) {
    int idx = blockIdx.x * blockDim.x + threadIdx.x;
    int k = idx >> 9, n = idx & (NPAD - 1);
    g_DT[idx] = (n < DIM6c) ? f2tf32(Dout[(size_t)k * DIM6c + n]) : 0u;
}

// ============ kBmma: g_HH = sig @ Dout, tf32 mma, cp.async 2-stage =========
#define SSTR 136
__global__ __launch_bounds__(256) void kBmma() {
    __shared__ unsigned int As[2][16][SSTR];   // [k][m]
    __shared__ unsigned int Bs[2][16][SSTR];   // [k][n]
    const int n0 = blockIdx.x * 128;
    const int m0 = blockIdx.y * 128;
    const int tid = threadIdx.x;
    const int wid = tid >> 5, lane = tid & 31;
    const int wm = wid >> 1, wn = wid & 1;
    const int lr = lane >> 2;
    const int lc = lane & 3;

    float acc[2][8][4];
    #pragma unroll
    for (int mi = 0; mi < 2; mi++)
        #pragma unroll
        for (int nj = 0; nj < 8; nj++)
            #pragma unroll
            for (int r = 0; r < 4; r++) acc[mi][nj][r] = 0.f;

    const int ld_row0 = tid >> 5;
    const int ld_row1 = ld_row0 + 8;
    const int ld_c4   = (tid & 31) * 4;

    auto issue = [&](int buf, int k0) {
        CP_ASYNC16(smem_u32(&As[buf][ld_row0][ld_c4]),
                   g_sigT + (size_t)(k0 + ld_row0) * MROWS + m0 + ld_c4);
        CP_ASYNC16(smem_u32(&As[buf][ld_row1][ld_c4]),
                   g_sigT + (size_t)(k0 + ld_row1) * MROWS + m0 + ld_c4);
        CP_ASYNC16(smem_u32(&Bs[buf][ld_row0][ld_c4]),
                   g_DT + (size_t)(k0 + ld_row0) * NPAD + n0 + ld_c4);
        CP_ASYNC16(smem_u32(&Bs[buf][ld_row1][ld_c4]),
                   g_DT + (size_t)(k0 + ld_row1) * NPAD + n0 + ld_c4);
    };

    issue(0, 0);  CP_COMMIT();
    issue(1, 16); CP_COMMIT();

    const int NIT = Gc / 16;
    for (int it = 0; it < NIT; it++) {
        const int buf = it & 1;
        CP_WAIT1();
        __syncthreads();

        #pragma unroll
        for (int kc = 0; kc < 2; kc++) {
            const int kb = kc * 8;
            unsigned int afr[2][4];
            #pragma unroll
            for (int mi = 0; mi < 2; mi++) {
                int rb = wm*32 + mi*16 + lr;
                afr[mi][0] = As[buf][kb + lc    ][rb    ];
                afr[mi][1] = As[buf][kb + lc    ][rb + 8];
                afr[mi][2] = As[buf][kb + lc + 4][rb    ];
                afr[mi][3] = As[buf][kb + lc + 4][rb + 8];
            }
            #pragma unroll
            for (int nj = 0; nj < 8; nj++) {
                int nb = wn*64 + nj*8 + lr;
                unsigned int b0 = Bs[buf][kb + lc    ][nb];
                unsigned int b1 = Bs[buf][kb + lc + 4][nb];
                #pragma unroll
                for (int mi = 0; mi < 2; mi++)
                    MMA_TF32(acc[mi][nj][0], acc[mi][nj][1], acc[mi][nj][2], acc[mi][nj][3],
                             afr[mi][0], afr[mi][1], afr[mi][2], afr[mi][3], b0, b1);
            }
        }
        __syncthreads();
        int nk = (it + 2) * 16;
        if (nk < Gc) issue(buf, nk);
        CP_COMMIT();
    }

    #pragma unroll
    for (int mi = 0; mi < 2; mi++) {
        #pragma unroll
        for (int nj = 0; nj < 8; nj++) {
            int row = m0 + wm*32 + mi*16 + lr;
            int col = n0 + wn*64 + nj*8 + lc*2;
            if (col < DIM6c) {
                g_HH[(size_t)row * DIM6c + col] = acc[mi][nj][0];
                if (col + 1 < DIM6c) g_HH[(size_t)row * DIM6c + col + 1] = acc[mi][nj][1];
                g_HH[(size_t)(row + 8) * DIM6c + col] = acc[mi][nj][2];
                if (col + 1 < DIM6c) g_HH[(size_t)(row + 8) * DIM6c + col + 1] = acc[mi][nj][3];
            }
        }
    }
}

// ============ kTr: g_A[l][(f*d+u)][(bt*d+m)] = tf32(g_HH[bt*16+f][OFF+u*d+m]) ===
template<int L, int OFF, int ABASE>
__device__ __forceinline__ void kTr_body() {
    constexpr int d  = 2*L + 1;
    constexpr int d2 = d * d;
    constexpr int Mdim = 512 * d;
    const int bt = blockIdx.x;
    const float* src = g_HH + (size_t)(bt * 16) * DIM6c;
    for (int j = threadIdx.x; j < 16 * d2; j += 256) {
        int f  = j / d2;
        int r  = j - f * d2;            // u*d + m
        int fu = j / d;                 // f*d + u
        int m  = j - fu * d;
        g_A[ABASE + (size_t)fu * Mdim + bt * d + m] = f2tf32(src[f * DIM6c + OFF + r]);
    }
}
__global__ __launch_bounds__(256) void kTr() {
    switch (blockIdx.y) {
        case 0: kTr_body<0,0,  AB0>(); break;
        case 1: kTr_body<1,1,  AB1>(); break;
        case 2: kTr_body<2,10, AB2>(); break;
        case 3: kTr_body<3,35, AB3>(); break;
        case 4: kTr_body<4,84, AB4>(); break;
        case 5: kTr_body<5,165,AB5>(); break;
        case 6: kTr_body<6,286,AB6>(); break;
    }
}

// ============ kWt: g_B[l][(f*d+u)][(g2*d+v)] = tf32(w2[f][g2][u][v]) ===
template<int L, int BBASE>
__device__ __forceinline__ void kWt_body(const float* __restrict__ wl) {
    constexpr int d = 2*L + 1;
    constexpr int Ndim = 64 * d;
    int idx = blockIdx.x * 256 + threadIdx.x;
    if (idx >= 16 * d * Ndim) return;
    int k = idx / Ndim, n = idx - k * Ndim;
    int f = k / d, u = k - f * d;
    int g2 = n / d, v = n - g2 * d;
    g_B[BBASE + idx] = f2tf32(wl[((f*64 + g2) * d + u) * d + v]);
}
__global__ __launch_bounds__(256) void kWt(
    const float* w0, const float* w1, const float* w2p, const float* w3,
    const float* w4, const float* w5, const float* w6) {
    switch (blockIdx.y) {
        case 0: kWt_body<0,BB0>(w0);  break;
        case 1: kWt_body<1,BB1>(w1);  break;
        case 2: kWt_body<2,BB2>(w2p); break;
        case 3: kWt_body<3,BB3>(w3);  break;
        case 4: kWt_body<4,BB4>(w4);  break;
        case 5: kWt_body<5,BB5>(w5);  break;
        case 6: kWt_body<6,BB6>(w6);  break;
    }
}

// ============ kCgemm: per-l C = A_l @ B_l (tf32 mma), scatter to g_TJ ===
// BM=128, BN=64, BK=16; M=512d, N=64d, K=16d (exact multiples)
template<int L, int OFF, int ABASE, int BBASE>
__device__ __forceinline__ void kCmma_body(unsigned int (*As)[136],
                                           unsigned int (*Bs)[72]) {
    constexpr int d    = 2*L + 1;
    constexpr int Mdim = 512 * d;
    constexpr int Ndim = 64 * d;
    constexpr int K    = 16 * d;
    constexpr int TM   = Mdim / 128;   // 4d
    constexpr int TN   = Ndim / 64;    // d
    const int tile = blockIdx.x;
    if (tile >= TM * TN) return;
    const int m0 = (tile % TM) * 128;
    const int n0 = (tile / TM) * 64;
    const int tid = threadIdx.x;
    const int wid = tid >> 5, lane = tid & 31;
    const int wm = wid >> 1, wn = wid & 1;
    const int lr = lane >> 2, lc = lane & 3;

    float acc[2][4][4];
    #pragma unroll
    for (int mi = 0; mi < 2; mi++)
        #pragma unroll
        for (int nj = 0; nj < 4; nj++)
            #pragma unroll
            for (int r = 0; r < 4; r++) acc[mi][nj][r] = 0.f;

    for (int k0 = 0; k0 < K; k0 += 16) {
        #pragma unroll
        for (int i = 0; i < 2; i++) {
            int idx = tid + i*256;             // 0..511
            int k = idx >> 5, c4 = (idx & 31) * 4;
            *(uint4*)&As[k][c4] =
                *(const uint4*)(g_A + ABASE + (size_t)(k0 + k) * Mdim + m0 + c4);
        }
        {
            int k = tid >> 4, c4 = (tid & 15) * 4;
            *(uint4*)&Bs[k][c4] =
                *(const uint4*)(g_B + BBASE + (size_t)(k0 + k) * Ndim + n0 + c4);
        }
        __syncthreads();

        #pragma unroll
        for (int kc = 0; kc < 2; kc++) {
            const int kb = kc * 8;
            unsigned int afr[2][4];
            #pragma unroll
            for (int mi = 0; mi < 2; mi++) {
                int rb = wm*32 + mi*16 + lr;
                afr[mi][0] = As[kb + lc    ][rb    ];
                afr[mi][1] = As[kb + lc    ][rb + 8];
                afr[mi][2] = As[kb + lc + 4][rb    ];
                afr[mi][3] = As[kb + lc + 4][rb + 8];
            }
            #pragma unroll
            for (int nj = 0; nj < 4; nj++) {
                int nb = wn*32 + nj*8 + lr;
                unsigned int b0 = Bs[kb + lc    ][nb];
                unsigned int b1 = Bs[kb + lc + 4][nb];
                #pragma unroll
                for (int mi = 0; mi < 2; mi++)
                    MMA_TF32(acc[mi][nj][0], acc[mi][nj][1], acc[mi][nj][2], acc[mi][nj][3],
                             afr[mi][0], afr[mi][1], afr[mi][2], afr[mi][3], b0, b1);
            }
        }
        __syncthreads();
    }

    const float scale = 0.25f * rsqrtf((float)d);
    #pragma unroll
    for (int mi = 0; mi < 2; mi++) {
        #pragma unroll
        for (int nj = 0; nj < 4; nj++) {
            #pragma unroll
            for (int rr = 0; rr < 2; rr++) {
                int row = m0 + wm*32 + mi*16 + lr + rr*8;
                int bt = row / d, mm = row - bt * d;
                #pragma unroll
                for (int cc = 0; cc < 2; cc++) {
                    int col = n0 + wn*32 + nj*8 + lc*2 + cc;
                    int g2 = col / d, v = col - g2 * d;
                    g_TJ[(size_t)(bt*64 + g2) * DIM6c + OFF + v*d + mm] =
                        acc[mi][nj][rr*2 + cc] * scale;
                }
            }
        }
    }
}
__global__ __launch_bounds__(256) void kCgemm() {
    __shared__ unsigned int As[16][136];
    __shared__ unsigned int Bs[16][72];
    switch (blockIdx.y) {
        case 0: kCmma_body<0,0,  AB0,BB0>(As,Bs); break;
        case 1: kCmma_body<1,1,  AB1,BB1>(As,Bs); break;
        case 2: kCmma_body<2,10, AB2,BB2>(As,Bs); break;
        case 3: kCmma_body<3,35, AB3,BB3>(As,Bs); break;
        case 4: kCmma_body<4,84, AB4,BB4>(As,Bs); break;
        case 5: kCmma_body<5,165,AB5,BB5>(As,Bs); break;
        case 6: kCmma_body<6,286,AB6,BB6>(As,Bs); break;
    }
}

// ============ kDmma: out[r][i] = sum_j A[r][j] * ico[i][j], tf32 mma ========
__global__ __launch_bounds__(256) void kDmma(const float* __restrict__ x,
                                             const float* __restrict__ ico,
                                             float* __restrict__ out, int I) {
    __shared__ unsigned int As[128][36];
    __shared__ unsigned int Bs[64][36];
    const int r0 = blockIdx.x * 128;
    const float* Ap = (r0 < XROWS) ? (x + (size_t)r0 * DIM6c)
                                   : (g_TJ + (size_t)(r0 - XROWS) * DIM6c);
    const int tid = threadIdx.x;
    const int wid = tid >> 5, lane = tid & 31;
    const int wm = wid >> 1, wn = wid & 1;
    const int lr = lane >> 2;
    const int lc = lane & 3;

    float acc[2][4][4];
    #pragma unroll
    for (int mi = 0; mi < 2; mi++)
        #pragma unroll
        for (int nj = 0; nj < 4; nj++)
            #pragma unroll
            for (int r = 0; r < 4; r++) acc[mi][nj][r] = 0.f;

    for (int j0 = 0; j0 < 480; j0 += 32) {
        #pragma unroll
        for (int i = 0; i < 16; i++) {
            int idx = i*256 + tid;
            int r = idx >> 5, kk = idx & 31;
            int j = j0 + kk;
            As[r][kk] = (j < DIM6c) ? f2tf32(Ap[(size_t)r * DIM6c + j]) : 0u;
        }
        #pragma unroll
        for (int i = 0; i < 8; i++) {
            int idx = i*256 + tid;
            int n = idx >> 5, kk = idx & 31;
            int j = j0 + kk;
            Bs[n][kk] = (n < I && j < DIM6c) ? f2tf32(ico[(size_t)n * DIM6c + j]) : 0u;
        }
        __syncthreads();

        #pragma unroll
        for (int kc = 0; kc < 4; kc++) {
            const int kb = kc * 8;
            unsigned int afr[2][4];
            #pragma unroll
            for (int mi = 0; mi < 2; mi++) {
                int rb = wm*32 + mi*16 + lr;
                afr[mi][0] = As[rb    ][kb + lc    ];
                afr[mi][1] = As[rb + 8][kb + lc    ];
                afr[mi][2] = As[rb    ][kb + lc + 4];
                afr[mi][3] = As[rb + 8][kb + lc + 4];
            }
            #pragma unroll
            for (int nj = 0; nj < 4; nj++) {
                int nb = wn*32 + nj*8 + lr;
                unsigned int b0 = Bs[nb][kb + lc    ];
                unsigned int b1 = Bs[nb][kb + lc + 4];
                #pragma unroll
                for (int mi = 0; mi < 2; mi++)
                    MMA_TF32(acc[mi][nj][0], acc[mi][nj][1], acc[mi][nj][2], acc[mi][nj][3],
                             afr[mi][0], afr[mi][1], afr[mi][2], afr[mi][3], b0, b1);
            }
        }
        __syncthreads();
    }

    #pragma unroll
    for (int mi = 0; mi < 2; mi++) {
        #pragma unroll
        for (int nj = 0; nj < 4; nj++) {
            int row = r0 + wm*32 + mi*16 + lr;
            int col = wn*32 + nj*8 + lc*2;
            if (col < I) {
                out[(size_t)row * I + col] = acc[mi][nj][0];
                out[(size_t)(row + 8) * I + col] = acc[mi][nj][2];
                if (col + 1 < I) {
                    out[(size_t)row * I + col + 1] = acc[mi][nj][1];
                    out[(size_t)(row + 8) * I + col + 1] = acc[mi][nj][3];
                }
            }
        }
    }
}

extern "C" void kernel_launch(void* const* d_in, const int* in_sizes, int n_in,
                              void* d_out, int out_size) {
    const float *x = nullptr, *traj = nullptr, *w1s = nullptr, *w1v = nullptr;
    const float *Din = nullptr, *Dout = nullptr, *ico = nullptr;
    const float* w2[7] = {};
    int icoN = 60;

    for (int i = 0; i < n_in; i++) {
        int sz = in_sizes[i];
        const float* p = (const float*)d_in[i];
        switch (sz) {
            case 7454720: x    = p; break;
            case 5120:    traj = p; break;
            case 16:      w1s  = p; break;
            case 144:     w1v  = p; break;
            case 40960:   Din  = p; break;
            case 1863680: Dout = p; break;
            case 1024:    w2[0] = p; break;
            case 9216:    w2[1] = p; break;
            case 25600:   w2[2] = p; break;
            case 50176:   w2[3] = p; break;
            case 82944:   w2[4] = p; break;
            case 123904:  w2[5] = p; break;
            case 173056:  w2[6] = p; break;
            default:      ico = p; icoN = sz / DIM6c; break;
        }
    }
    float* out = (float*)d_out;

    kH<<<MROWS/256, 256>>>(traj, w1s, w1v);
    kCvt<<<(Gc * NPAD) / 256, 256>>>(Dout);
    kSigT<<<dim3(MROWS/256, Gc/8), 256>>>(Din);
    kWt<<<dim3(676, 7), 256>>>(w2[0], w2[1], w2[2], w2[3], w2[4], w2[5], w2[6]);

    kBmma<<<dim3(4, MROWS/128), 256>>>();

    kTr<<<dim3(BTc, 7), 256>>>();
    kCgemm<<<dim3(676, 7), 256>>>();

    kDmma<<<(XROWS + TROWS)/128, 256>>>(x, ico, out, icoN);
}

// round 6
// speedup vs baseline: 5.2118x; 1.0250x over previous
#include <cuda_runtime.h>
#include <math.h>

#define F8c   16
#define F2c   64
#define DIM6c 455
#define Gc    4096
#define MROWS 8192     // B*T*F8
#define BTc   512      // B*T
#define XROWS 16384    // B*H*C
#define TROWS 32768    // B*T*F2
#define NPAD  512

__device__ __forceinline__ unsigned int f2tf32(float f) {
    unsigned int r;
    asm("cvt.rna.tf32.f32 %0, %1;" : "=r"(r) : "f"(f));
    return r;
}

__device__ __forceinline__ unsigned int smem_u32(const void* p) {
    return (unsigned int)__cvta_generic_to_shared(p);
}
#define CP_ASYNC16(dst, src) \
    asm volatile("cp.async.cg.shared.global [%0], [%1], 16;" :: "r"(dst), "l"(src))
#define CP_COMMIT()  asm volatile("cp.async.commit_group;")
#define CP_WAIT1()   asm volatile("cp.async.wait_group 1;")

#define MMA_TF32(c0,c1,c2,c3,a0,a1,a2,a3,b0,b1) \
    asm volatile("mma.sync.aligned.m16n8k8.row.col.f32.tf32.tf32.f32 " \
        "{%0,%1,%2,%3}, {%4,%5,%6,%7}, {%8,%9}, {%0,%1,%2,%3};" \
        : "+f"(c0), "+f"(c1), "+f"(c2), "+f"(c3) \
        : "r"(a0), "r"(a1), "r"(a2), "r"(a3), "r"(b0), "r"(b1))

// -------- scratch --------
__device__ float        g_H  [MROWS * 10];
__device__ unsigned int g_sigT[(size_t)Gc * MROWS];    // tf32 sig, [k][m]
__device__ unsigned int g_DT [(size_t)Gc * NPAD];      // tf32 Dout, [k][n]
__device__ unsigned int g_A [8192 * 455];              // per-l A_l [(f*d+u)][(bt*d+m)]
__device__ unsigned int g_B [1024 * 455];              // per-l B_l [(f*d+u)][(g2*d+v)]
__device__ float        g_TJ[BTc * F2c * DIM6c];

// per-l cumulative bases (cum d^2 = 0,1,10,35,84,165,286)
#define AB0 0
#define AB1 (8192*1)
#define AB2 (8192*10)
#define AB3 (8192*35)
#define AB4 (8192*84)
#define AB5 (8192*165)
#define AB6 (8192*286)
#define BB0 0
#define BB1 (1024*1)
#define BB2 (1024*10)
#define BB3 (1024*35)
#define BB4 (1024*84)
#define BB5 (1024*165)
#define BB6 (1024*286)

// ================= kernel H =================
__global__ void kH(const float* __restrict__ traj,
                   const float* __restrict__ w1s,
                   const float* __restrict__ w1v) {
    int row = blockIdx.x * blockDim.x + threadIdx.x;
    if (row >= MROWS) return;
    int bt = row >> 4, c = row & 15;
    const float* tr = traj + bt * 10;
    float tv[9];
    #pragma unroll
    for (int q = 0; q < 9; q++) tv[q] = tr[q];
    float s = tr[9];
    float* out = g_H + row * 10;
    out[0] = s * w1s[c];
    const float inv3 = 0.57735026918962576f;
    #pragma unroll
    for (int v = 0; v < 3; v++) {
        #pragma unroll
        for (int m = 0; m < 3; m++) {
            float a = 0.f;
            #pragma unroll
            for (int u = 0; u < 3; u++)
                a += tv[u*3 + m] * w1v[c*9 + u*3 + v];
            out[1 + v*3 + m] = a * inv3;
        }
    }
}

// ============ kSigT: g_sigT[k][m] = tf32(relu(H[m].Din[k])) ============
__global__ __launch_bounds__(256) void kSigT(const float* __restrict__ Din) {
    __shared__ float Ds[8][10];
    const int m  = blockIdx.x * 256 + threadIdx.x;
    const int k0 = blockIdx.y * 8;
    if (threadIdx.x < 80)
        Ds[threadIdx.x / 10][threadIdx.x % 10] = Din[k0*10 + threadIdx.x];
    __syncthreads();
    float h[10];
    #pragma unroll
    for (int q = 0; q < 10; q++) h[q] = g_H[m*10 + q];
    #pragma unroll
    for (int kk = 0; kk < 8; kk++) {
        float a = 0.f;
        #pragma unroll
        for (int q = 0; q < 10; q++) a += h[q] * Ds[kk][q];
        g_sigT[(size_t)(k0 + kk) * MROWS + m] = f2tf32(fmaxf(a, 0.f));
    }
}

// ============ kCvt: Dout padded tf32 copy ============
__global__ void kCvt(const float* __restrict__ Dout) {
    int idx = blockIdx.x * blockDim.x + threadIdx.x;
    int k = idx >> 9, n = idx & (NPAD - 1);
    g_DT[idx] = (n < DIM6c) ? f2tf32(Dout[(size_t)k * DIM6c + n]) : 0u;
}

// ===== scatter one C element of the big GEMM straight into per-l tf32 A =====
__device__ __forceinline__ void scatterA(int row, int col, float val) {
    if (col >= DIM6c) return;
    unsigned int tv = f2tf32(val);
    int bt = row >> 4, f = row & 15;
    if (col < 1) {
        g_A[AB0 + f * 512 + bt] = tv;
    } else if (col < 10) {
        int r = col - 1, u = r / 3, m = r - u*3;
        g_A[AB1 + (f*3 + u) * (512*3) + bt*3 + m] = tv;
    } else if (col < 35) {
        int r = col - 10, u = r / 5, m = r - u*5;
        g_A[AB2 + (f*5 + u) * (512*5) + bt*5 + m] = tv;
    } else if (col < 84) {
        int r = col - 35, u = r / 7, m = r - u*7;
        g_A[AB3 + (f*7 + u) * (512*7) + bt*7 + m] = tv;
    } else if (col < 165) {
        int r = col - 84, u = r / 9, m = r - u*9;
        g_A[AB4 + (f*9 + u) * (512*9) + bt*9 + m] = tv;
    } else if (col < 286) {
        int r = col - 165, u = r / 11, m = r - u*11;
        g_A[AB5 + (f*11 + u) * (512*11) + bt*11 + m] = tv;
    } else {
        int r = col - 286, u = r / 13, m = r - u*13;
        g_A[AB6 + (f*13 + u) * (512*13) + bt*13 + m] = tv;
    }
}

// ============ kBmma: per-l A = (sig @ Dout) permuted, tf32 mma ============
// BM=128, BN=128, BK=32, 2-stage cp.async (dynamic smem), A-frag double buffer
#define SSTR 136
#define ASZ  (32 * SSTR)
__global__ __launch_bounds__(256, 2) void kBmma() {
    extern __shared__ unsigned int sm[];
    // layout: A stages [0..2*ASZ), B stages [2*ASZ..4*ASZ)
    const int n0 = blockIdx.x * 128;
    const int m0 = blockIdx.y * 128;
    const int tid = threadIdx.x;
    const int wid = tid >> 5, lane = tid & 31;
    const int wm = wid >> 1, wn = wid & 1;
    const int lr = lane >> 2;
    const int lc = lane & 3;

    float acc[2][8][4];
    #pragma unroll
    for (int mi = 0; mi < 2; mi++)
        #pragma unroll
        for (int nj = 0; nj < 8; nj++)
            #pragma unroll
            for (int r = 0; r < 4; r++) acc[mi][nj][r] = 0.f;

    auto issue = [&](int buf, int k0) {
        #pragma unroll
        for (int i = 0; i < 4; i++) {
            int idx = tid + i*256;
            int row = idx >> 5, c4 = (idx & 31) * 4;
            CP_ASYNC16(smem_u32(&sm[buf*ASZ + row*SSTR + c4]),
                       g_sigT + (size_t)(k0 + row) * MROWS + m0 + c4);
            CP_ASYNC16(smem_u32(&sm[2*ASZ + buf*ASZ + row*SSTR + c4]),
                       g_DT + (size_t)(k0 + row) * NPAD + n0 + c4);
        }
    };

    issue(0, 0);  CP_COMMIT();
    issue(1, 32); CP_COMMIT();

    const int rb0 = wm*32 + lr;
    const int NIT = Gc / 32;  // 128
    for (int it = 0; it < NIT; it++) {
        const int buf = it & 1;
        const unsigned int* Ab = sm + buf*ASZ;
        const unsigned int* Bb = sm + 2*ASZ + buf*ASZ;
        CP_WAIT1();
        __syncthreads();

        unsigned int afr[2][2][4];   // [pingpong][mi][frag]
        #pragma unroll
        for (int mi = 0; mi < 2; mi++) {
            int rb = rb0 + mi*16;
            afr[0][mi][0] = Ab[(lc    )*SSTR + rb    ];
            afr[0][mi][1] = Ab[(lc    )*SSTR + rb + 8];
            afr[0][mi][2] = Ab[(lc + 4)*SSTR + rb    ];
            afr[0][mi][3] = Ab[(lc + 4)*SSTR + rb + 8];
        }
        #pragma unroll
        for (int kc = 0; kc < 4; kc++) {
            const int cur = kc & 1, nxt = cur ^ 1;
            if (kc < 3) {
                const int kb = (kc + 1) * 8;
                #pragma unroll
                for (int mi = 0; mi < 2; mi++) {
                    int rb = rb0 + mi*16;
                    afr[nxt][mi][0] = Ab[(kb + lc    )*SSTR + rb    ];
                    afr[nxt][mi][1] = Ab[(kb + lc    )*SSTR + rb + 8];
                    afr[nxt][mi][2] = Ab[(kb + lc + 4)*SSTR + rb    ];
                    afr[nxt][mi][3] = Ab[(kb + lc + 4)*SSTR + rb + 8];
                }
            }
            const int kb = kc * 8;
            #pragma unroll
            for (int nj = 0; nj < 8; nj++) {
                int nb = wn*64 + nj*8 + lr;
                unsigned int b0 = Bb[(kb + lc    )*SSTR + nb];
                unsigned int b1 = Bb[(kb + lc + 4)*SSTR + nb];
                #pragma unroll
                for (int mi = 0; mi < 2; mi++)
                    MMA_TF32(acc[mi][nj][0], acc[mi][nj][1], acc[mi][nj][2], acc[mi][nj][3],
                             afr[cur][mi][0], afr[cur][mi][1],
                             afr[cur][mi][2], afr[cur][mi][3], b0, b1);
            }
        }
        __syncthreads();
        int nk = (it + 2) * 32;
        if (nk < Gc) issue(buf, nk);
        CP_COMMIT();
    }

    // epilogue: scatter directly into per-l tf32 A layout
    #pragma unroll
    for (int mi = 0; mi < 2; mi++) {
        #pragma unroll
        for (int nj = 0; nj < 8; nj++) {
            int row = m0 + wm*32 + mi*16 + lr;
            int col = n0 + wn*64 + nj*8 + lc*2;
            scatterA(row,     col,     acc[mi][nj][0]);
            scatterA(row,     col + 1, acc[mi][nj][1]);
            scatterA(row + 8, col,     acc[mi][nj][2]);
            scatterA(row + 8, col + 1, acc[mi][nj][3]);
        }
    }
}

// ============ kWt: g_B[l][(f*d+u)][(g2*d+v)] = tf32(w2[f][g2][u][v]) ===
template<int L, int BBASE>
__device__ __forceinline__ void kWt_body(const float* __restrict__ wl) {
    constexpr int d = 2*L + 1;
    constexpr int Ndim = 64 * d;
    int idx = blockIdx.x * 256 + threadIdx.x;
    if (idx >= 16 * d * Ndim) return;
    int k = idx / Ndim, n = idx - k * Ndim;
    int f = k / d, u = k - f * d;
    int g2 = n / d, v = n - g2 * d;
    g_B[BBASE + idx] = f2tf32(wl[((f*64 + g2) * d + u) * d + v]);
}
__global__ __launch_bounds__(256) void kWt(
    const float* w0, const float* w1, const float* w2p, const float* w3,
    const float* w4, const float* w5, const float* w6) {
    switch (blockIdx.y) {
        case 0: kWt_body<0,BB0>(w0);  break;
        case 1: kWt_body<1,BB1>(w1);  break;
        case 2: kWt_body<2,BB2>(w2p); break;
        case 3: kWt_body<3,BB3>(w3);  break;
        case 4: kWt_body<4,BB4>(w4);  break;
        case 5: kWt_body<5,BB5>(w5);  break;
        case 6: kWt_body<6,BB6>(w6);  break;
    }
}

// ============ kCgemm: per-l C = A_l @ B_l (tf32 mma), scatter to g_TJ ===
template<int L, int OFF, int ABASE, int BBASE>
__device__ __forceinline__ void kCmma_body(unsigned int (*As)[136],
                                           unsigned int (*Bs)[72]) {
    constexpr int d    = 2*L + 1;
    constexpr int Mdim = 512 * d;
    constexpr int Ndim = 64 * d;
    constexpr int K    = 16 * d;
    constexpr int TM   = Mdim / 128;
    constexpr int TN   = Ndim / 64;
    const int tile = blockIdx.x;
    if (tile >= TM * TN) return;
    const int m0 = (tile % TM) * 128;
    const int n0 = (tile / TM) * 64;
    const int tid = threadIdx.x;
    const int wid = tid >> 5, lane = tid & 31;
    const int wm = wid >> 1, wn = wid & 1;
    const int lr = lane >> 2, lc = lane & 3;

    float acc[2][4][4];
    #pragma unroll
    for (int mi = 0; mi < 2; mi++)
        #pragma unroll
        for (int nj = 0; nj < 4; nj++)
            #pragma unroll
            for (int r = 0; r < 4; r++) acc[mi][nj][r] = 0.f;

    for (int k0 = 0; k0 < K; k0 += 16) {
        #pragma unroll
        for (int i = 0; i < 2; i++) {
            int idx = tid + i*256;
            int k = idx >> 5, c4 = (idx & 31) * 4;
            *(uint4*)&As[k][c4] =
                *(const uint4*)(g_A + ABASE + (size_t)(k0 + k) * Mdim + m0 + c4);
        }
        {
            int k = tid >> 4, c4 = (tid & 15) * 4;
            *(uint4*)&Bs[k][c4] =
                *(const uint4*)(g_B + BBASE + (size_t)(k0 + k) * Ndim + n0 + c4);
        }
        __syncthreads();

        #pragma unroll
        for (int kc = 0; kc < 2; kc++) {
            const int kb = kc * 8;
            unsigned int afr[2][4];
            #pragma unroll
            for (int mi = 0; mi < 2; mi++) {
                int rb = wm*32 + mi*16 + lr;
                afr[mi][0] = As[kb + lc    ][rb    ];
                afr[mi][1] = As[kb + lc    ][rb + 8];
                afr[mi][2] = As[kb + lc + 4][rb    ];
                afr[mi][3] = As[kb + lc + 4][rb + 8];
            }
            #pragma unroll
            for (int nj = 0; nj < 4; nj++) {
                int nb = wn*32 + nj*8 + lr;
                unsigned int b0 = Bs[kb + lc    ][nb];
                unsigned int b1 = Bs[kb + lc + 4][nb];
                #pragma unroll
                for (int mi = 0; mi < 2; mi++)
                    MMA_TF32(acc[mi][nj][0], acc[mi][nj][1], acc[mi][nj][2], acc[mi][nj][3],
                             afr[mi][0], afr[mi][1], afr[mi][2], afr[mi][3], b0, b1);
            }
        }
        __syncthreads();
    }

    const float scale = 0.25f * rsqrtf((float)d);
    #pragma unroll
    for (int mi = 0; mi < 2; mi++) {
        #pragma unroll
        for (int nj = 0; nj < 4; nj++) {
            #pragma unroll
            for (int rr = 0; rr < 2; rr++) {
                int row = m0 + wm*32 + mi*16 + lr + rr*8;
                int bt = row / d, mm = row - bt * d;
                #pragma unroll
                for (int cc = 0; cc < 2; cc++) {
                    int col = n0 + wn*32 + nj*8 + lc*2 + cc;
                    int g2 = col / d, v = col - g2 * d;
                    g_TJ[(size_t)(bt*64 + g2) * DIM6c + OFF + v*d + mm] =
                        acc[mi][nj][rr*2 + cc] * scale;
                }
            }
        }
    }
}
__global__ __launch_bounds__(256) void kCgemm() {
    __shared__ unsigned int As[16][136];
    __shared__ unsigned int Bs[16][72];
    switch (blockIdx.y) {
        case 0: kCmma_body<0,0,  AB0,BB0>(As,Bs); break;
        case 1: kCmma_body<1,1,  AB1,BB1>(As,Bs); break;
        case 2: kCmma_body<2,10, AB2,BB2>(As,Bs); break;
        case 3: kCmma_body<3,35, AB3,BB3>(As,Bs); break;
        case 4: kCmma_body<4,84, AB4,BB4>(As,Bs); break;
        case 5: kCmma_body<5,165,AB5,BB5>(As,Bs); break;
        case 6: kCmma_body<6,286,AB6,BB6>(As,Bs); break;
    }
}

// ============ kDmma: out[r][i] = sum_j A[r][j] * ico[i][j], tf32 mma ========
__global__ __launch_bounds__(256) void kDmma(const float* __restrict__ x,
                                             const float* __restrict__ ico,
                                             float* __restrict__ out, int I) {
    __shared__ unsigned int As[128][36];
    __shared__ unsigned int Bs[64][36];
    const int r0 = blockIdx.x * 128;
    const float* Ap = (r0 < XROWS) ? (x + (size_t)r0 * DIM6c)
                                   : (g_TJ + (size_t)(r0 - XROWS) * DIM6c);
    const int tid = threadIdx.x;
    const int wid = tid >> 5, lane = tid & 31;
    const int wm = wid >> 1, wn = wid & 1;
    const int lr = lane >> 2;
    const int lc = lane & 3;

    float acc[2][4][4];
    #pragma unroll
    for (int mi = 0; mi < 2; mi++)
        #pragma unroll
        for (int nj = 0; nj < 4; nj++)
            #pragma unroll
            for (int r = 0; r < 4; r++) acc[mi][nj][r] = 0.f;

    for (int j0 = 0; j0 < 480; j0 += 32) {
        #pragma unroll
        for (int i = 0; i < 16; i++) {
            int idx = i*256 + tid;
            int r = idx >> 5, kk = idx & 31;
            int j = j0 + kk;
            As[r][kk] = (j < DIM6c) ? f2tf32(Ap[(size_t)r * DIM6c + j]) : 0u;
        }
        #pragma unroll
        for (int i = 0; i < 8; i++) {
            int idx = i*256 + tid;
            int n = idx >> 5, kk = idx & 31;
            int j = j0 + kk;
            Bs[n][kk] = (n < I && j < DIM6c) ? f2tf32(ico[(size_t)n * DIM6c + j]) : 0u;
        }
        __syncthreads();

        #pragma unroll
        for (int kc = 0; kc < 4; kc++) {
            const int kb = kc * 8;
            unsigned int afr[2][4];
            #pragma unroll
            for (int mi = 0; mi < 2; mi++) {
                int rb = wm*32 + mi*16 + lr;
                afr[mi][0] = As[rb    ][kb + lc    ];
                afr[mi][1] = As[rb + 8][kb + lc    ];
                afr[mi][2] = As[rb    ][kb + lc + 4];
                afr[mi][3] = As[rb + 8][kb + lc + 4];
            }
            #pragma unroll
            for (int nj = 0; nj < 4; nj++) {
                int nb = wn*32 + nj*8 + lr;
                unsigned int b0 = Bs[nb][kb + lc    ];
                unsigned int b1 = Bs[nb][kb + lc + 4];
                #pragma unroll
                for (int mi = 0; mi < 2; mi++)
                    MMA_TF32(acc[mi][nj][0], acc[mi][nj][1], acc[mi][nj][2], acc[mi][nj][3],
                             afr[mi][0], afr[mi][1], afr[mi][2], afr[mi][3], b0, b1);
            }
        }
        __syncthreads();
    }

    #pragma unroll
    for (int mi = 0; mi < 2; mi++) {
        #pragma unroll
        for (int nj = 0; nj < 4; nj++) {
            int row = r0 + wm*32 + mi*16 + lr;
            int col = wn*32 + nj*8 + lc*2;
            if (col < I) {
                out[(size_t)row * I + col] = acc[mi][nj][0];
                out[(size_t)(row + 8) * I + col] = acc[mi][nj][2];
                if (col + 1 < I) {
                    out[(size_t)row * I + col + 1] = acc[mi][nj][1];
                    out[(size_t)(row + 8) * I + col + 1] = acc[mi][nj][3];
                }
            }
        }
    }
}

extern "C" void kernel_launch(void* const* d_in, const int* in_sizes, int n_in,
                              void* d_out, int out_size) {
    const float *x = nullptr, *traj = nullptr, *w1s = nullptr, *w1v = nullptr;
    const float *Din = nullptr, *Dout = nullptr, *ico = nullptr;
    const float* w2[7] = {};
    int icoN = 60;

    for (int i = 0; i < n_in; i++) {
        int sz = in_sizes[i];
        const float* p = (const float*)d_in[i];
        switch (sz) {
            case 7454720: x    = p; break;
            case 5120:    traj = p; break;
            case 16:      w1s  = p; break;
            case 144:     w1v  = p; break;
            case 40960:   Din  = p; break;
            case 1863680: Dout = p; break;
            case 1024:    w2[0] = p; break;
            case 9216:    w2[1] = p; break;
            case 25600:   w2[2] = p; break;
            case 50176:   w2[3] = p; break;
            case 82944:   w2[4] = p; break;
            case 123904:  w2[5] = p; break;
            case 173056:  w2[6] = p; break;
            default:      ico = p; icoN = sz / DIM6c; break;
        }
    }
    float* out = (float*)d_out;

    const int SMEMB = 4 * ASZ * 4;   // 69632 bytes
    cudaFuncSetAttribute(kBmma, cudaFuncAttributeMaxDynamicSharedMemorySize, SMEMB);

    kH<<<MROWS/256, 256>>>(traj, w1s, w1v);
    kCvt<<<(Gc * NPAD) / 256, 256>>>(Dout);
    kSigT<<<dim3(MROWS/256, Gc/8), 256>>>(Din);
    kWt<<<dim3(676, 7), 256>>>(w2[0], w2[1], w2[2], w2[3], w2[4], w2[5], w2[6]);

    kBmma<<<dim3(4, MROWS/128), 256, SMEMB>>>();

    kCgemm<<<dim3(676, 7), 256>>>();

    kDmma<<<(XROWS + TROWS)/128, 256>>>(x, ico, out, icoN);
}

// round 8
// speedup vs baseline: 7.1775x; 1.3772x over previous
#include <cuda_runtime.h>
#include <cuda_fp16.h>
#include <math.h>

#define F8c   16
#define F2c   64
#define DIM6c 455
#define Gc    4096
#define MROWS 8192     // B*T*F8
#define BTc   512      // B*T
#define XROWS 16384    // B*H*C
#define TROWS 32768    // B*T*F2
#define NBPAD 512
#define DSCALE   256.0f
#define DUNSCALE (1.0f/256.0f)

__device__ __forceinline__ unsigned int f2tf32(float f) {
    unsigned int r;
    asm("cvt.rna.tf32.f32 %0, %1;" : "=r"(r) : "f"(f));
    return r;
}
__device__ __forceinline__ unsigned int smem_u32(const void* p) {
    return (unsigned int)__cvta_generic_to_shared(p);
}
#define CP_ASYNC16(dst, src) \
    asm volatile("cp.async.cg.shared.global [%0], [%1], 16;" :: "r"(dst), "l"(src))
#define CP_COMMIT()  asm volatile("cp.async.commit_group;")
#define CP_WAIT1()   asm volatile("cp.async.wait_group 1;")

#define MMA_TF32(c0,c1,c2,c3,a0,a1,a2,a3,b0,b1) \
    asm volatile("mma.sync.aligned.m16n8k8.row.col.f32.tf32.tf32.f32 " \
        "{%0,%1,%2,%3}, {%4,%5,%6,%7}, {%8,%9}, {%0,%1,%2,%3};" \
        : "+f"(c0), "+f"(c1), "+f"(c2), "+f"(c3) \
        : "r"(a0), "r"(a1), "r"(a2), "r"(a3), "r"(b0), "r"(b1))

#define MMA_F16(c0,c1,c2,c3,a0,a1,a2,a3,b0,b1) \
    asm volatile("mma.sync.aligned.m16n8k16.row.col.f32.f16.f16.f32 " \
        "{%0,%1,%2,%3}, {%4,%5,%6,%7}, {%8,%9}, {%0,%1,%2,%3};" \
        : "+f"(c0), "+f"(c1), "+f"(c2), "+f"(c3) \
        : "r"(a0), "r"(a1), "r"(a2), "r"(a3), "r"(b0), "r"(b1))

// -------- scratch --------
__device__ float          g_H  [MROWS * 10];
__device__ __half         g_sigH[(size_t)MROWS * Gc];   // fp16 sig, [m][k], 67MB
__device__ __half         g_BnH [(size_t)NBPAD * Gc];   // fp16 Dout^T * 256, [n][k]
__device__ unsigned int   g_A [8192 * 455];             // per-l A_l tf32
__device__ unsigned int   g_B [1024 * 455];             // per-l B_l tf32
__device__ float          g_TJ[BTc * F2c * DIM6c];

#define AB0 0
#define AB1 (8192*1)
#define AB2 (8192*10)
#define AB3 (8192*35)
#define AB4 (8192*84)
#define AB5 (8192*165)
#define AB6 (8192*286)
#define BB0 0
#define BB1 (1024*1)
#define BB2 (1024*10)
#define BB3 (1024*35)
#define BB4 (1024*84)
#define BB5 (1024*165)
#define BB6 (1024*286)

// ================= kernel H =================
__global__ void kH(const float* __restrict__ traj,
                   const float* __restrict__ w1s,
                   const float* __restrict__ w1v) {
    int row = blockIdx.x * blockDim.x + threadIdx.x;
    if (row >= MROWS) return;
    int bt = row >> 4, c = row & 15;
    const float* tr = traj + bt * 10;
    float tv[9];
    #pragma unroll
    for (int q = 0; q < 9; q++) tv[q] = tr[q];
    float s = tr[9];
    float* out = g_H + row * 10;
    out[0] = s * w1s[c];
    const float inv3 = 0.57735026918962576f;
    #pragma unroll
    for (int v = 0; v < 3; v++) {
        #pragma unroll
        for (int m = 0; m < 3; m++) {
            float a = 0.f;
            #pragma unroll
            for (int u = 0; u < 3; u++)
                a += tv[u*3 + m] * w1v[c*9 + u*3 + v];
            out[1 + v*3 + m] = a * inv3;
        }
    }
}

// ============ kSig: g_sigH[m][k] = fp16(relu(H[m].Din[k])) ============
__global__ __launch_bounds__(256) void kSig(const float* __restrict__ Din) {
    __shared__ float Hs[32][10];
    const int m0 = blockIdx.y * 32;
    const int k  = blockIdx.x * 256 + threadIdx.x;
    for (int i = threadIdx.x; i < 320; i += 256)
        Hs[i/10][i%10] = g_H[m0*10 + i];
    __syncthreads();
    float dr[10];
    #pragma unroll
    for (int q = 0; q < 10; q++) dr[q] = Din[k*10 + q];
    #pragma unroll 4
    for (int m = 0; m < 32; m++) {
        float a = 0.f;
        #pragma unroll
        for (int q = 0; q < 10; q++) a += Hs[m][q] * dr[q];
        g_sigH[(size_t)(m0 + m) * Gc + k] = __float2half_rn(fmaxf(a, 0.f));
    }
}

// ============ kCvtT: g_BnH[n][k] = fp16(Dout[k][n] * 256) ============
__global__ __launch_bounds__(256) void kCvtT(const float* __restrict__ Dout) {
    __shared__ unsigned short t[32][33];
    const int k0 = blockIdx.x * 32;
    const int n0 = blockIdx.y * 32;
    const int tx = threadIdx.x & 31, ty = threadIdx.x >> 5;   // 32 x 8
    #pragma unroll
    for (int j = 0; j < 4; j++) {
        int k = k0 + ty + j*8, n = n0 + tx;
        float v = (n < DIM6c) ? Dout[(size_t)k * DIM6c + n] * DSCALE : 0.f;
        t[ty + j*8][tx] = __half_as_ushort(__float2half_rn(v));
    }
    __syncthreads();
    #pragma unroll
    for (int j = 0; j < 4; j++) {
        int n = n0 + ty + j*8, k = k0 + tx;
        g_BnH[(size_t)n * Gc + k] = __ushort_as_half(t[tx][ty + j*8]);
    }
}

// ===== scatter one C element straight into per-l tf32 A =====
__device__ __forceinline__ void scatterA(int row, int col, float val) {
    if (col >= DIM6c) return;
    unsigned int tv = f2tf32(val);
    int bt = row >> 4, f = row & 15;
    if (col < 1) {
        g_A[AB0 + f * 512 + bt] = tv;
    } else if (col < 10) {
        int r = col - 1, u = r / 3, m = r - u*3;
        g_A[AB1 + (f*3 + u) * (512*3) + bt*3 + m] = tv;
    } else if (col < 35) {
        int r = col - 10, u = r / 5, m = r - u*5;
        g_A[AB2 + (f*5 + u) * (512*5) + bt*5 + m] = tv;
    } else if (col < 84) {
        int r = col - 35, u = r / 7, m = r - u*7;
        g_A[AB3 + (f*7 + u) * (512*7) + bt*7 + m] = tv;
    } else if (col < 165) {
        int r = col - 84, u = r / 9, m = r - u*9;
        g_A[AB4 + (f*9 + u) * (512*9) + bt*9 + m] = tv;
    } else if (col < 286) {
        int r = col - 165, u = r / 11, m = r - u*11;
        g_A[AB5 + (f*11 + u) * (512*11) + bt*11 + m] = tv;
    } else {
        int r = col - 286, u = r / 13, m = r - u*13;
        g_A[AB6 + (f*13 + u) * (512*13) + bt*13 + m] = tv;
    }
}

// ============ kBh: fp16 mma GEMM. CTA 128x128, BK=64, 2-stage cp.async ====
// smem halves, row stride 72 halves (144B): word stride 36 == 4 mod 32 -> no conflicts
#define HSTR 72
#define STAGE_B 18432              // 128*72*2 bytes
__global__ __launch_bounds__(256) void kBh() {
    extern __shared__ __align__(16) char smb[];
    // A0@0, A1@STAGE_B, B0@2*STAGE_B, B1@3*STAGE_B
    const int n0 = blockIdx.x * 128;
    const int m0 = blockIdx.y * 128;
    const int tid = threadIdx.x;
    const int wid = tid >> 5, lane = tid & 31;
    const int wm = wid >> 1, wn = wid & 1;
    const int lr = lane >> 2;
    const int lc = lane & 3;

    float acc[2][8][4];
    #pragma unroll
    for (int mi = 0; mi < 2; mi++)
        #pragma unroll
        for (int nj = 0; nj < 8; nj++)
            #pragma unroll
            for (int r = 0; r < 4; r++) acc[mi][nj][r] = 0.f;

    auto issue = [&](int buf, int k0) {
        #pragma unroll
        for (int i = 0; i < 4; i++) {
            int id = tid + i*256;              // 0..1023
            int row = id >> 3, cc = id & 7;    // 8 x 16B chunks per 128B row
            CP_ASYNC16(smem_u32(smb + buf*STAGE_B + row*144 + cc*16),
                       g_sigH + (size_t)(m0 + row) * Gc + k0 + cc*8);
            CP_ASYNC16(smem_u32(smb + 2*STAGE_B + buf*STAGE_B + row*144 + cc*16),
                       g_BnH + (size_t)(n0 + row) * Gc + k0 + cc*8);
        }
    };

    issue(0, 0);  CP_COMMIT();
    issue(1, 64); CP_COMMIT();

    const int rb0 = wm*32 + lr;
    const int NIT = Gc / 64;   // 64
    for (int it = 0; it < NIT; it++) {
        const int buf = it & 1;
        const unsigned int* A32 = (const unsigned int*)(smb + buf*STAGE_B);
        const unsigned int* B32 = (const unsigned int*)(smb + 2*STAGE_B + buf*STAGE_B);
        CP_WAIT1();
        __syncthreads();

        #pragma unroll
        for (int kc = 0; kc < 4; kc++) {
            const int w0 = kc*8 + lc;          // word offset in 36-word row
            unsigned int afr[2][4];
            #pragma unroll
            for (int mi = 0; mi < 2; mi++) {
                int rb = rb0 + mi*16;
                afr[mi][0] = A32[(rb    )*36 + w0    ];
                afr[mi][1] = A32[(rb + 8)*36 + w0    ];
                afr[mi][2] = A32[(rb    )*36 + w0 + 4];
                afr[mi][3] = A32[(rb + 8)*36 + w0 + 4];
            }
            #pragma unroll
            for (int nj = 0; nj < 8; nj++) {
                int nb = wn*64 + nj*8 + lr;
                unsigned int b0 = B32[nb*36 + w0    ];
                unsigned int b1 = B32[nb*36 + w0 + 4];
                #pragma unroll
                for (int mi = 0; mi < 2; mi++)
                    MMA_F16(acc[mi][nj][0], acc[mi][nj][1], acc[mi][nj][2], acc[mi][nj][3],
                            afr[mi][0], afr[mi][1], afr[mi][2], afr[mi][3], b0, b1);
            }
        }
        __syncthreads();
        int nk = (it + 2) * 64;
        if (nk < Gc) issue(buf, nk);
        CP_COMMIT();
    }

    // epilogue: unscale and scatter into per-l tf32 A layout
    #pragma unroll
    for (int mi = 0; mi < 2; mi++) {
        #pragma unroll
        for (int nj = 0; nj < 8; nj++) {
            int row = m0 + wm*32 + mi*16 + lr;
            int col = n0 + wn*64 + nj*8 + lc*2;
            scatterA(row,     col,     acc[mi][nj][0] * DUNSCALE);
            scatterA(row,     col + 1, acc[mi][nj][1] * DUNSCALE);
            scatterA(row + 8, col,     acc[mi][nj][2] * DUNSCALE);
            scatterA(row + 8, col + 1, acc[mi][nj][3] * DUNSCALE);
        }
    }
}

// ============ kWt: g_B[l][(f*d+u)][(g2*d+v)] = tf32(w2[f][g2][u][v]) ===
template<int L, int BBASE>
__device__ __forceinline__ void kWt_body(const float* __restrict__ wl) {
    constexpr int d = 2*L + 1;
    constexpr int Ndim = 64 * d;
    int idx = blockIdx.x * 256 + threadIdx.x;
    if (idx >= 16 * d * Ndim) return;
    int k = idx / Ndim, n = idx - k * Ndim;
    int f = k / d, u = k - f * d;
    int g2 = n / d, v = n - g2 * d;
    g_B[BBASE + idx] = f2tf32(wl[((f*64 + g2) * d + u) * d + v]);
}
__global__ __launch_bounds__(256) void kWt(
    const float* w0, const float* w1, const float* w2p, const float* w3,
    const float* w4, const float* w5, const float* w6) {
    switch (blockIdx.y) {
        case 0: kWt_body<0,BB0>(w0);  break;
        case 1: kWt_body<1,BB1>(w1);  break;
        case 2: kWt_body<2,BB2>(w2p); break;
        case 3: kWt_body<3,BB3>(w3);  break;
        case 4: kWt_body<4,BB4>(w4);  break;
        case 5: kWt_body<5,BB5>(w5);  break;
        case 6: kWt_body<6,BB6>(w6);  break;
    }
}

// ============ kCgemm: per-l C = A_l @ B_l (tf32 mma.sync), scatter to g_TJ ===
template<int L, int OFF, int ABASE, int BBASE>
__device__ __forceinline__ void kCmma_body(unsigned int (*As)[136],
                                           unsigned int (*Bs)[72]) {
    constexpr int d    = 2*L + 1;
    constexpr int Mdim = 512 * d;
    constexpr int Ndim = 64 * d;
    constexpr int K    = 16 * d;
    constexpr int TM   = Mdim / 128;
    constexpr int TN   = Ndim / 64;
    const int tile = blockIdx.x;
    if (tile >= TM * TN) return;
    const int m0 = (tile % TM) * 128;
    const int n0 = (tile / TM) * 64;
    const int tid = threadIdx.x;
    const int wid = tid >> 5, lane = tid & 31;
    const int wm = wid >> 1, wn = wid & 1;
    const int lr = lane >> 2, lc = lane & 3;

    float acc[2][4][4];
    #pragma unroll
    for (int mi = 0; mi < 2; mi++)
        #pragma unroll
        for (int nj = 0; nj < 4; nj++)
            #pragma unroll
            for (int r = 0; r < 4; r++) acc[mi][nj][r] = 0.f;

    for (int k0 = 0; k0 < K; k0 += 16) {
        #pragma unroll
        for (int i = 0; i < 2; i++) {
            int idx = tid + i*256;
            int k = idx >> 5, c4 = (idx & 31) * 4;
            *(uint4*)&As[k][c4] =
                *(const uint4*)(g_A + ABASE + (size_t)(k0 + k) * Mdim + m0 + c4);
        }
        {
            int k = tid >> 4, c4 = (tid & 15) * 4;
            *(uint4*)&Bs[k][c4] =
                *(const uint4*)(g_B + BBASE + (size_t)(k0 + k) * Ndim + n0 + c4);
        }
        __syncthreads();

        #pragma unroll
        for (int kc = 0; kc < 2; kc++) {
            const int kb = kc * 8;
            unsigned int afr[2][4];
            #pragma unroll
            for (int mi = 0; mi < 2; mi++) {
                int rb = wm*32 + mi*16 + lr;
                afr[mi][0] = As[kb + lc    ][rb    ];
                afr[mi][1] = As[kb + lc    ][rb + 8];
                afr[mi][2] = As[kb + lc + 4][rb    ];
                afr[mi][3] = As[kb + lc + 4][rb + 8];
            }
            #pragma unroll
            for (int nj = 0; nj < 4; nj++) {
                int nb = wn*32 + nj*8 + lr;
                unsigned int b0 = Bs[kb + lc    ][nb];
                unsigned int b1 = Bs[kb + lc + 4][nb];
                #pragma unroll
                for (int mi = 0; mi < 2; mi++)
                    MMA_TF32(acc[mi][nj][0], acc[mi][nj][1], acc[mi][nj][2], acc[mi][nj][3],
                             afr[mi][0], afr[mi][1], afr[mi][2], afr[mi][3], b0, b1);
            }
        }
        __syncthreads();
    }

    const float scale = 0.25f * rsqrtf((float)d);
    #pragma unroll
    for (int mi = 0; mi < 2; mi++) {
        #pragma unroll
        for (int nj = 0; nj < 4; nj++) {
            #pragma unroll
            for (int rr = 0; rr < 2; rr++) {
                int row = m0 + wm*32 + mi*16 + lr + rr*8;
                int bt = row / d, mm = row - bt * d;
                #pragma unroll
                for (int cc = 0; cc < 2; cc++) {
                    int col = n0 + wn*32 + nj*8 + lc*2 + cc;
                    int g2 = col / d, v = col - g2 * d;
                    g_TJ[(size_t)(bt*64 + g2) * DIM6c + OFF + v*d + mm] =
                        acc[mi][nj][rr*2 + cc] * scale;
                }
            }
        }
    }
}
__global__ __launch_bounds__(256) void kCgemm() {
    __shared__ unsigned int As[16][136];
    __shared__ unsigned int Bs[16][72];
    switch (blockIdx.y) {
        case 0: kCmma_body<0,0,  AB0,BB0>(As,Bs); break;
        case 1: kCmma_body<1,1,  AB1,BB1>(As,Bs); break;
        case 2: kCmma_body<2,10, AB2,BB2>(As,Bs); break;
        case 3: kCmma_body<3,35, AB3,BB3>(As,Bs); break;
        case 4: kCmma_body<4,84, AB4,BB4>(As,Bs); break;
        case 5: kCmma_body<5,165,AB5,BB5>(As,Bs); break;
        case 6: kCmma_body<6,286,AB6,BB6>(As,Bs); break;
    }
}

// ============ kDmma: out[r][i] = sum_j A[r][j] * ico[i][j], tf32 mma.sync ===
__global__ __launch_bounds__(256) void kDmma(const float* __restrict__ x,
                                             const float* __restrict__ ico,
                                             float* __restrict__ out, int I) {
    __shared__ unsigned int As[128][36];
    __shared__ unsigned int Bs[64][36];
    const int r0 = blockIdx.x * 128;
    const float* Ap = (r0 < XROWS) ? (x + (size_t)r0 * DIM6c)
                                   : (g_TJ + (size_t)(r0 - XROWS) * DIM6c);
    const int tid = threadIdx.x;
    const int wid = tid >> 5, lane = tid & 31;
    const int wm = wid >> 1, wn = wid & 1;
    const int lr = lane >> 2;
    const int lc = lane & 3;

    float acc[2][4][4];
    #pragma unroll
    for (int mi = 0; mi < 2; mi++)
        #pragma unroll
        for (int nj = 0; nj < 4; nj++)
            #pragma unroll
            for (int r = 0; r < 4; r++) acc[mi][nj][r] = 0.f;

    for (int j0 = 0; j0 < 480; j0 += 32) {
        #pragma unroll
        for (int i = 0; i < 16; i++) {
            int idx = i*256 + tid;
            int r = idx >> 5, kk = idx & 31;
            int j = j0 + kk;
            As[r][kk] = (j < DIM6c) ? f2tf32(Ap[(size_t)r * DIM6c + j]) : 0u;
        }
        #pragma unroll
        for (int i = 0; i < 8; i++) {
            int idx = i*256 + tid;
            int n = idx >> 5, kk = idx & 31;
            int j = j0 + kk;
            Bs[n][kk] = (n < I && j < DIM6c) ? f2tf32(ico[(size_t)n * DIM6c + j]) : 0u;
        }
        __syncthreads();

        #pragma unroll
        for (int kc = 0; kc < 4; kc++) {
            const int kb = kc * 8;
            unsigned int afr[2][4];
            #pragma unroll
            for (int mi = 0; mi < 2; mi++) {
                int rb = wm*32 + mi*16 + lr;
                afr[mi][0] = As[rb    ][kb + lc    ];
                afr[mi][1] = As[rb + 8][kb + lc    ];
                afr[mi][2] = As[rb    ][kb + lc + 4];
                afr[mi][3] = As[rb + 8][kb + lc + 4];
            }
            #pragma unroll
            for (int nj = 0; nj < 4; nj++) {
                int nb = wn*32 + nj*8 + lr;
                unsigned int b0 = Bs[nb][kb + lc    ];
                unsigned int b1 = Bs[nb][kb + lc + 4];
                #pragma unroll
                for (int mi = 0; mi < 2; mi++)
                    MMA_TF32(acc[mi][nj][0], acc[mi][nj][1], acc[mi][nj][2], acc[mi][nj][3],
                             afr[mi][0], afr[mi][1], afr[mi][2], afr[mi][3], b0, b1);
            }
        }
        __syncthreads();
    }

    #pragma unroll
    for (int mi = 0; mi < 2; mi++) {
        #pragma unroll
        for (int nj = 0; nj < 4; nj++) {
            int row = r0 + wm*32 + mi*16 + lr;
            int col = wn*32 + nj*8 + lc*2;
            if (col < I) {
                out[(size_t)row * I + col] = acc[mi][nj][0];
                out[(size_t)(row + 8) * I + col] = acc[mi][nj][2];
                if (col + 1 < I) {
                    out[(size_t)row * I + col + 1] = acc[mi][nj][1];
                    out[(size_t)(row + 8) * I + col + 1] = acc[mi][nj][3];
                }
            }
        }
    }
}

extern "C" void kernel_launch(void* const* d_in, const int* in_sizes, int n_in,
                              void* d_out, int out_size) {
    const float *x = nullptr, *traj = nullptr, *w1s = nullptr, *w1v = nullptr;
    const float *Din = nullptr, *Dout = nullptr, *ico = nullptr;
    const float* w2[7] = {};
    int icoN = 60;

    for (int i = 0; i < n_in; i++) {
        int sz = in_sizes[i];
        const float* p = (const float*)d_in[i];
        switch (sz) {
            case 7454720: x    = p; break;
            case 5120:    traj = p; break;
            case 16:      w1s  = p; break;
            case 144:     w1v  = p; break;
            case 40960:   Din  = p; break;
            case 1863680: Dout = p; break;
            case 1024:    w2[0] = p; break;
            case 9216:    w2[1] = p; break;
            case 25600:   w2[2] = p; break;
            case 50176:   w2[3] = p; break;
            case 82944:   w2[4] = p; break;
            case 123904:  w2[5] = p; break;
            case 173056:  w2[6] = p; break;
            default:      ico = p; icoN = sz / DIM6c; break;
        }
    }
    float* out = (float*)d_out;

    const int SMEMB = 4 * STAGE_B;   // 73728 bytes
    cudaFuncSetAttribute(kBh, cudaFuncAttributeMaxDynamicSharedMemorySize, SMEMB);

    kH<<<MROWS/256, 256>>>(traj, w1s, w1v);
    kCvtT<<<dim3(Gc/32, NBPAD/32), 256>>>(Dout);
    kSig<<<dim3(Gc/256, MROWS/32), 256>>>(Din);
    kWt<<<dim3(676, 7), 256>>>(w2[0], w2[1], w2[2], w2[3], w2[4], w2[5], w2[6]);

    kBh<<<dim3(4, MROWS/128), 256, SMEMB>>>();

    kCgemm<<<dim3(676, 7), 256>>>();

    kDmma<<<(XROWS + TROWS)/128, 256>>>(x, ico, out, icoN);
}